// round 1
// baseline (speedup 1.0000x reference)
#include <cuda_runtime.h>
#include <math.h>

#define N_NODES 131072
#define N_DST   16384
#define DEG     16
#define N_EDGES (N_DST*DEG)
#define HID     256

// Scratch for node embeddings h[N_NODES][256] (device global: no allocations allowed)
__device__ float g_h[(size_t)N_NODES * HID];
__device__ int   g_is64;

__device__ __forceinline__ float gelu_exact(float x){
    return 0.5f * x * (1.0f + erff(x * 0.70710678118654752f));
}

// ---------------------------------------------------------------------------
// mesh_edges dtype detection. dst column is repeat(arange(16384),16).
// int32 layout: word[2e]=dst, word[2e+1]=src  -> word[32] = dst[16] = 1
// int64 layout: word[4e]=dst_lo,...           -> word[32] = dst[8]  = 0
// ---------------------------------------------------------------------------
__global__ void detect_kernel(const int* __restrict__ me32){
    if (threadIdx.x == 0 && blockIdx.x == 0){
        g_is64 = (me32[32] != 1) ? 1 : 0;
    }
}

// ---------------------------------------------------------------------------
// Node encoder: h = ip3( gelu( ip2( gelu( ip1(x) ) ) ) ) + [cos|sin](2*pi*pos@Bf^T)
// 64 nodes per block, 256 threads, fused in SMEM.
// ---------------------------------------------------------------------------
#define ENC_NT 64
#define ENC_KT 16
#define ENC_LDA 257   // sA/sB row stride (floats), odd -> conflict free
#define ENC_LDW 17    // sW row stride

#define ENC_SMEM_FLOATS (ENC_NT*ENC_LDA*2 + 256*ENC_LDW + ENC_NT*3 + ENC_NT*2)

__global__ __launch_bounds__(256, 1)
void encoder_kernel(const float* __restrict__ x,
                    const float* __restrict__ mesh_pos,
                    const float* __restrict__ w1, const float* __restrict__ b1,
                    const float* __restrict__ w2, const float* __restrict__ b2,
                    const float* __restrict__ w3, const float* __restrict__ b3,
                    const float* __restrict__ bf)
{
    extern __shared__ float sm[];
    float* sA = sm;                         // [64][257] layer activations
    float* sB = sA + ENC_NT*ENC_LDA;        // [64][257]
    float* sW = sB + ENC_NT*ENC_LDA;        // [256][17] weight k-slab
    float* sX = sW + 256*ENC_LDW;           // [64][3]
    float* sP = sX + ENC_NT*3;              // [64][2]

    const int t  = threadIdx.x;
    const int n0 = blockIdx.x * ENC_NT;
    const int og = t & 31;      // lane
    const int ng = t >> 5;      // warp id -> node group (8 nodes)

    // stage x and mesh_pos
    for (int i = t; i < ENC_NT*3; i += 256) sX[i] = x[(size_t)n0*3 + i];
    for (int i = t; i < ENC_NT*2; i += 256) sP[i] = mesh_pos[(size_t)n0*2 + i];
    __syncthreads();

    // ---- layer 1: h1 = gelu(W1 x + b1), thread t owns out dim o = t ----
    {
        const float wa = w1[t*3+0], wb = w1[t*3+1], wc = w1[t*3+2], bb = b1[t];
        for (int n = 0; n < ENC_NT; n++){
            float v = fmaf(wa, sX[n*3+0], fmaf(wb, sX[n*3+1], fmaf(wc, sX[n*3+2], bb)));
            sA[n*ENC_LDA + t] = gelu_exact(v);
        }
    }
    __syncthreads();

    // ---- layer 2: h2 = gelu(W2 h1 + b2)  (sA -> sB) ----
    {
        float acc[8][8];
        #pragma unroll
        for (int i = 0; i < 8; i++)
            #pragma unroll
            for (int j = 0; j < 8; j++) acc[i][j] = 0.f;

        for (int kt = 0; kt < HID; kt += ENC_KT){
            __syncthreads();
            #pragma unroll
            for (int oo = 0; oo < 256; oo += 16){
                int o  = oo + (t >> 4);
                int kk = t & 15;
                sW[o*ENC_LDW + kk] = w2[o*HID + kt + kk];
            }
            __syncthreads();
            #pragma unroll
            for (int kk = 0; kk < ENC_KT; kk++){
                const int k = kt + kk;
                float a[8], w[8];
                #pragma unroll
                for (int i = 0; i < 8; i++) a[i] = sA[(ng*8+i)*ENC_LDA + k];
                #pragma unroll
                for (int j = 0; j < 8; j++) w[j] = sW[(og + 32*j)*ENC_LDW + kk];
                #pragma unroll
                for (int i = 0; i < 8; i++)
                    #pragma unroll
                    for (int j = 0; j < 8; j++)
                        acc[i][j] = fmaf(a[i], w[j], acc[i][j]);
            }
        }
        __syncthreads();
        #pragma unroll
        for (int j = 0; j < 8; j++){
            const int o = og + 32*j;
            const float bb = b2[o];
            #pragma unroll
            for (int i = 0; i < 8; i++)
                sB[(ng*8+i)*ENC_LDA + o] = gelu_exact(acc[i][j] + bb);
        }
    }
    __syncthreads();

    // ---- layer 3: h = W3 h2 + b3 + fourier  (sB -> g_h) ----
    {
        float acc[8][8];
        #pragma unroll
        for (int i = 0; i < 8; i++)
            #pragma unroll
            for (int j = 0; j < 8; j++) acc[i][j] = 0.f;

        for (int kt = 0; kt < HID; kt += ENC_KT){
            __syncthreads();
            #pragma unroll
            for (int oo = 0; oo < 256; oo += 16){
                int o  = oo + (t >> 4);
                int kk = t & 15;
                sW[o*ENC_LDW + kk] = w3[o*HID + kt + kk];
            }
            __syncthreads();
            #pragma unroll
            for (int kk = 0; kk < ENC_KT; kk++){
                const int k = kt + kk;
                float a[8], w[8];
                #pragma unroll
                for (int i = 0; i < 8; i++) a[i] = sB[(ng*8+i)*ENC_LDA + k];
                #pragma unroll
                for (int j = 0; j < 8; j++) w[j] = sW[(og + 32*j)*ENC_LDW + kk];
                #pragma unroll
                for (int i = 0; i < 8; i++)
                    #pragma unroll
                    for (int j = 0; j < 8; j++)
                        acc[i][j] = fmaf(a[i], w[j], acc[i][j]);
            }
        }
        #pragma unroll
        for (int j = 0; j < 8; j++){
            const int o   = og + 32*j;
            const float bb = b3[o];
            const int of  = (o < 128) ? o : (o - 128);
            const float bfa = bf[of*2+0];
            const float bfb = bf[of*2+1];
            #pragma unroll
            for (int i = 0; i < 8; i++){
                const int n = ng*8 + i;
                const float proj = 6.283185307179586f * (sP[n*2+0]*bfa + sP[n*2+1]*bfb);
                const float four = (o < 128) ? cosf(proj) : sinf(proj);
                g_h[(size_t)(n0 + n)*HID + o] = acc[i][j] + bb + four;
            }
        }
    }
}

// ---------------------------------------------------------------------------
// Edge MLP + segment mean. 32 edges (= 2 dsts) per block, 256 threads.
// in = [h[src] | h[dst]] (512) -> gelu(512x512) -> gelu(256x512) -> 256x256
// out[d] = mean over 16 edges.
// ---------------------------------------------------------------------------
#define EDG_ET  32
#define EDG_KT  16
#define EDG_LD1 516   // stride for 512-wide rows (mult of 4, /4 odd -> ok)
#define EDG_LD2 260   // stride for 256-wide rows
#define EDG_LDW 17

#define EDG_SMEM_FLOATS (EDG_ET*EDG_LD1*2 + EDG_ET*EDG_LD2 + 512*EDG_LDW)
#define EDG_SMEM_BYTES  (EDG_SMEM_FLOATS*4 + 2*EDG_ET*4)

__global__ __launch_bounds__(256, 1)
void edge_kernel(const int* __restrict__ me32,
                 const float* __restrict__ wm1, const float* __restrict__ bm1,
                 const float* __restrict__ wm2, const float* __restrict__ bm2,
                 const float* __restrict__ wm3, const float* __restrict__ bm3,
                 float* __restrict__ out)
{
    extern __shared__ float sm[];
    float* sIn = sm;                         // [32][516] input (also m3 at end)
    float* sM1 = sIn + EDG_ET*EDG_LD1;       // [32][516]
    float* sM2 = sM1 + EDG_ET*EDG_LD1;       // [32][260]
    float* sW  = sM2 + EDG_ET*EDG_LD2;       // [512][17]
    int*   sSrc = (int*)(sW + 512*EDG_LDW);  // [32]
    int*   sDst = sSrc + EDG_ET;             // [32]

    const int t  = threadIdx.x;
    const int e0 = blockIdx.x * EDG_ET;
    const int og = t & 31;
    const int ng = t >> 5;                   // edge group: 4 edges

    if (t < EDG_ET){
        const int e = e0 + t;
        int s, d;
        if (g_is64){ d = me32[4*e]; s = me32[4*e+2]; }
        else       { d = me32[2*e]; s = me32[2*e+1]; }
        sSrc[t] = s; sDst[t] = d;
    }
    __syncthreads();

    // gather: row r = [h[src_r] (256) | h[dst_r] (256)], float4 coalesced
    for (int idx = t; idx < EDG_ET*128; idx += 256){
        const int r  = idx >> 7;
        const int c4 = idx & 127;
        float4 v;
        if (c4 < 64) v = ((const float4*)(g_h + (size_t)sSrc[r]*HID))[c4];
        else         v = ((const float4*)(g_h + (size_t)sDst[r]*HID))[c4 - 64];
        *(float4*)(sIn + r*EDG_LD1 + c4*4) = v;
    }
    __syncthreads();

    // ---- layer 1: m1 = gelu(Wm1 in + bm1)  (512 out, K=512) ----
    {
        float acc[4][16];
        #pragma unroll
        for (int i = 0; i < 4; i++)
            #pragma unroll
            for (int j = 0; j < 16; j++) acc[i][j] = 0.f;

        for (int kt = 0; kt < 512; kt += EDG_KT){
            __syncthreads();
            #pragma unroll
            for (int oo = 0; oo < 512; oo += 16){
                int o  = oo + (t >> 4);
                int kk = t & 15;
                sW[o*EDG_LDW + kk] = wm1[o*512 + kt + kk];
            }
            __syncthreads();
            #pragma unroll
            for (int kk = 0; kk < EDG_KT; kk++){
                const int k = kt + kk;
                float a[4], w[16];
                #pragma unroll
                for (int i = 0; i < 4; i++) a[i] = sIn[(ng*4+i)*EDG_LD1 + k];
                #pragma unroll
                for (int j = 0; j < 16; j++) w[j] = sW[(og + 32*j)*EDG_LDW + kk];
                #pragma unroll
                for (int i = 0; i < 4; i++)
                    #pragma unroll
                    for (int j = 0; j < 16; j++)
                        acc[i][j] = fmaf(a[i], w[j], acc[i][j]);
            }
        }
        __syncthreads();
        #pragma unroll
        for (int j = 0; j < 16; j++){
            const int o = og + 32*j;
            const float bb = bm1[o];
            #pragma unroll
            for (int i = 0; i < 4; i++)
                sM1[(ng*4+i)*EDG_LD1 + o] = gelu_exact(acc[i][j] + bb);
        }
    }
    __syncthreads();

    // ---- layer 2: m2 = gelu(Wm2 m1 + bm2)  (256 out, K=512) ----
    {
        float acc[4][8];
        #pragma unroll
        for (int i = 0; i < 4; i++)
            #pragma unroll
            for (int j = 0; j < 8; j++) acc[i][j] = 0.f;

        for (int kt = 0; kt < 512; kt += EDG_KT){
            __syncthreads();
            #pragma unroll
            for (int oo = 0; oo < 256; oo += 16){
                int o  = oo + (t >> 4);
                int kk = t & 15;
                sW[o*EDG_LDW + kk] = wm2[o*512 + kt + kk];
            }
            __syncthreads();
            #pragma unroll
            for (int kk = 0; kk < EDG_KT; kk++){
                const int k = kt + kk;
                float a[4], w[8];
                #pragma unroll
                for (int i = 0; i < 4; i++) a[i] = sM1[(ng*4+i)*EDG_LD1 + k];
                #pragma unroll
                for (int j = 0; j < 8; j++) w[j] = sW[(og + 32*j)*EDG_LDW + kk];
                #pragma unroll
                for (int i = 0; i < 4; i++)
                    #pragma unroll
                    for (int j = 0; j < 8; j++)
                        acc[i][j] = fmaf(a[i], w[j], acc[i][j]);
            }
        }
        __syncthreads();
        #pragma unroll
        for (int j = 0; j < 8; j++){
            const int o = og + 32*j;
            const float bb = bm2[o];
            #pragma unroll
            for (int i = 0; i < 4; i++)
                sM2[(ng*4+i)*EDG_LD2 + o] = gelu_exact(acc[i][j] + bb);
        }
    }
    __syncthreads();

    // ---- layer 3: m3 = Wm3 m2 + bm3  (256 out, K=256), write into sM1 ----
    {
        float acc[4][8];
        #pragma unroll
        for (int i = 0; i < 4; i++)
            #pragma unroll
            for (int j = 0; j < 8; j++) acc[i][j] = 0.f;

        for (int kt = 0; kt < 256; kt += EDG_KT){
            __syncthreads();
            #pragma unroll
            for (int oo = 0; oo < 256; oo += 16){
                int o  = oo + (t >> 4);
                int kk = t & 15;
                sW[o*EDG_LDW + kk] = wm3[o*256 + kt + kk];
            }
            __syncthreads();
            #pragma unroll
            for (int kk = 0; kk < EDG_KT; kk++){
                const int k = kt + kk;
                float a[4], w[8];
                #pragma unroll
                for (int i = 0; i < 4; i++) a[i] = sM2[(ng*4+i)*EDG_LD2 + k];
                #pragma unroll
                for (int j = 0; j < 8; j++) w[j] = sW[(og + 32*j)*EDG_LDW + kk];
                #pragma unroll
                for (int i = 0; i < 4; i++)
                    #pragma unroll
                    for (int j = 0; j < 8; j++)
                        acc[i][j] = fmaf(a[i], w[j], acc[i][j]);
            }
        }
        __syncthreads();
        #pragma unroll
        for (int j = 0; j < 8; j++){
            const int o = og + 32*j;
            const float bb = bm3[o];
            #pragma unroll
            for (int i = 0; i < 4; i++)
                sM1[(ng*4+i)*EDG_LD1 + o] = acc[i][j] + bb;   // m3 rows
        }
    }
    __syncthreads();

    // ---- segment mean: 2 dsts x 256 outputs ----
    for (int idx = t; idx < 2*256; idx += 256){
        const int dl = idx >> 8;
        const int o  = idx & 255;
        float s = 0.f;
        #pragma unroll
        for (int i = 0; i < 16; i++) s += sM1[(dl*16 + i)*EDG_LD1 + o];
        out[(size_t)sDst[dl*16]*HID + o] = s * (1.0f/16.0f);
    }
}

// ---------------------------------------------------------------------------
extern "C" void kernel_launch(void* const* d_in, const int* in_sizes, int n_in,
                              void* d_out, int out_size)
{
    const float* x        = (const float*)d_in[0];
    const float* mesh_pos = (const float*)d_in[1];
    const int*   me32     = (const int*)  d_in[2];
    // d_in[3] = batch_idx (unused)
    const float* ip_w1 = (const float*)d_in[4];
    const float* ip_b1 = (const float*)d_in[5];
    const float* ip_w2 = (const float*)d_in[6];
    const float* ip_b2 = (const float*)d_in[7];
    const float* ip_w3 = (const float*)d_in[8];
    const float* ip_b3 = (const float*)d_in[9];
    const float* bf    = (const float*)d_in[10];
    const float* mw1   = (const float*)d_in[11];
    const float* mb1   = (const float*)d_in[12];
    const float* mw2   = (const float*)d_in[13];
    const float* mb2   = (const float*)d_in[14];
    const float* mw3   = (const float*)d_in[15];
    const float* mb3   = (const float*)d_in[16];
    float* out = (float*)d_out;

    const int enc_smem = ENC_SMEM_FLOATS * 4;
    const int edg_smem = EDG_SMEM_BYTES;
    cudaFuncSetAttribute(encoder_kernel, cudaFuncAttributeMaxDynamicSharedMemorySize, enc_smem);
    cudaFuncSetAttribute(edge_kernel,    cudaFuncAttributeMaxDynamicSharedMemorySize, edg_smem);

    detect_kernel<<<1, 32>>>(me32);
    encoder_kernel<<<N_NODES/ENC_NT, 256, enc_smem>>>(
        x, mesh_pos, ip_w1, ip_b1, ip_w2, ip_b2, ip_w3, ip_b3, bf);
    edge_kernel<<<N_EDGES/EDG_ET, 256, edg_smem>>>(
        me32, mw1, mb1, mw2, mb2, mw3, mb3, out);
}

// round 3
// speedup vs baseline: 4.4176x; 4.4176x over previous
#include <cuda_runtime.h>
#include <math.h>
#include <stdint.h>

#define N_NODES 131072
#define N_DST   16384
#define DEG     16
#define N_EDGES (N_DST*DEG)
#define HID     256

// ---------------- global scratch (device globals: no runtime alloc) --------
__device__ float g_bufA[(size_t)N_NODES * 256];   // h1, then h
__device__ float g_bufB[(size_t)N_NODES * 256];   // h2
__device__ float g_ea  [(size_t)N_NODES * 512];   // ea, reused as m2
__device__ float g_eb  [(size_t)N_DST   * 512];   // eb
__device__ float g_m1  [(size_t)N_EDGES * 512];   // m1
__device__ int   g_is64;

__device__ __forceinline__ float gelu_exact(float x){
    return 0.5f * x * (1.0f + erff(x * 0.70710678118654752f));
}
__device__ __forceinline__ uint32_t f2tf(float x){
    uint32_t r; asm("cvt.rna.tf32.f32 %0, %1;" : "=r"(r) : "f"(x)); return r;
}
__device__ __forceinline__ void mma8(float* c, const uint32_t* a, const uint32_t* b){
    asm volatile("mma.sync.aligned.m16n8k8.row.col.f32.tf32.tf32.f32 "
        "{%0,%1,%2,%3}, {%4,%5,%6,%7}, {%8,%9}, {%0,%1,%2,%3};"
        : "+f"(c[0]), "+f"(c[1]), "+f"(c[2]), "+f"(c[3])
        : "r"(a[0]), "r"(a[1]), "r"(a[2]), "r"(a[3]), "r"(b[0]), "r"(b[1]));
}

// ---------------------------------------------------------------------------
// mesh_edges dtype detection (dst col = repeat(arange(16384),16)):
// int32 layout -> word[32] == 1 ; int64 layout -> word[32] == 0
// ---------------------------------------------------------------------------
__global__ void detect_kernel(const int* __restrict__ me32){
    if (threadIdx.x == 0 && blockIdx.x == 0) g_is64 = (me32[32] != 1) ? 1 : 0;
}

// ---------------------------------------------------------------------------
// h1 = gelu(x @ W1^T + b1), K=3 (tiny): fp32. 64 nodes/block, thread t = out dim.
// ---------------------------------------------------------------------------
__global__ __launch_bounds__(256)
void h1_kernel(const float* __restrict__ x,
               const float* __restrict__ w1, const float* __restrict__ b1){
    __shared__ float sx[64*3];
    const int t  = threadIdx.x;
    const int n0 = blockIdx.x * 64;
    for (int i = t; i < 64*3; i += 256) sx[i] = x[(size_t)n0*3 + i];
    __syncthreads();
    const float wa = w1[t*3+0], wb = w1[t*3+1], wc = w1[t*3+2], bb = b1[t];
    for (int n = 0; n < 64; n++){
        float v = fmaf(wa, sx[n*3+0], fmaf(wb, sx[n*3+1], fmaf(wc, sx[n*3+2], bb)));
        g_bufA[(size_t)(n0+n)*256 + t] = gelu_exact(v);
    }
}

// ---------------------------------------------------------------------------
// m1 = gelu(ea[src] + eb[dst])  (262144 x 512), one float4 per thread.
// ---------------------------------------------------------------------------
__global__ __launch_bounds__(256)
void gather_m1_kernel(const int* __restrict__ me32){
    const size_t idx = (size_t)blockIdx.x * 256 + threadIdx.x;
    const int e  = (int)(idx >> 7);
    const int c4 = (int)(idx & 127);
    int s, d;
    if (g_is64){ d = me32[4*(size_t)e]; s = me32[4*(size_t)e + 2]; }
    else       { d = me32[2*(size_t)e]; s = me32[2*(size_t)e + 1]; }
    float4 a = *(const float4*)(g_ea + (size_t)s*512 + c4*4);
    float4 b = *(const float4*)(g_eb + (size_t)d*512 + c4*4);
    float4 o;
    o.x = gelu_exact(a.x + b.x);
    o.y = gelu_exact(a.y + b.y);
    o.z = gelu_exact(a.z + b.z);
    o.w = gelu_exact(a.w + b.w);
    *(float4*)(g_m1 + (size_t)e*512 + c4*4) = o;
}

// ---------------------------------------------------------------------------
// tf32 mma.sync GEMM: C[M x Ntot] = epi(A[M x K] @ W[Ntot x K]^T + bias)
// Block tile 128x256, BK=32, 256 threads = 8 warps (2x4), warp tile 64x64.
// SMEM staged in m16n8k8 fragment order (LDS.128 / LDS.64 consumers).
// EPI: 0=store(+bias), 1=gelu, 2=fourier(pos,bf), 3=segment-mean over 16 rows.
// ---------------------------------------------------------------------------
#define BM 128
#define BN 256
#define BK 32
#define NS 4                      // k8 slices per BK chunk
#define SA_FLOATS 4096            // (BM/16)*NS*32*4
#define SB_FLOATS 8192            // (BN/8)*NS*32*2
#define GEMM_SMEM ((2*SA_FLOATS + 2*SB_FLOATS)*4)   // 96 KB

template<int K, int EPI, bool HAS_BIAS>
__global__ __launch_bounds__(256, 1)
void gemm_mma_kernel(const float* __restrict__ A, int lda,
                     const float* __restrict__ W, int ldw,
                     const float* __restrict__ bias,
                     float* __restrict__ C, int ldc,
                     const float* __restrict__ pos,
                     const float* __restrict__ bfour)
{
    extern __shared__ float sm[];
    float* sAb[2] = { sm,                         sm + SA_FLOATS };
    float* sBb[2] = { sm + 2*SA_FLOATS,           sm + 2*SA_FLOATS + SB_FLOATS };

    const int t    = threadIdx.x;
    const int lane = t & 31;
    const int wid  = t >> 5;
    const int wm   = wid >> 2;        // 0..1
    const int wn   = wid & 3;         // 0..3
    const int gid  = lane >> 2;       // 0..7
    const int tig  = lane & 3;        // 0..3
    const int m0   = blockIdx.x * BM;
    const int n0   = blockIdx.y * BN;

    float acc[4][8][4];
    #pragma unroll
    for (int i = 0; i < 4; i++)
        #pragma unroll
        for (int j = 0; j < 8; j++)
            #pragma unroll
            for (int r = 0; r < 4; r++) acc[i][j][r] = 0.f;

    constexpr int NC = K / BK;
    float4 ra[4], rb[8];

    // ---- prologue: load chunk 0 ----
    #pragma unroll
    for (int it = 0; it < 4; it++){
        const int idx = it*256 + t, row = idx >> 3, c4 = idx & 7;
        ra[it] = *(const float4*)(A + (size_t)(m0 + row)*lda + c4*4);
    }
    #pragma unroll
    for (int it = 0; it < 8; it++){
        const int idx = it*256 + t, row = idx >> 3, c4 = idx & 7;
        rb[it] = *(const float4*)(W + (size_t)(n0 + row)*ldw + c4*4);
    }
    {
        float* sA = sAb[0]; float* sB = sBb[0];
        #pragma unroll
        for (int it = 0; it < 4; it++){
            const int idx = it*256 + t, row = idx >> 3, c4 = idx & 7;
            const int g = row >> 4, s = c4 >> 1;
            const int r = ((c4 & 1) << 1) | ((row >> 3) & 1);
            const int lb = (row & 7) * 4;
            const int base = ((g*NS + s)*32 + lb)*4 + r;
            sA[base     ] = __uint_as_float(f2tf(ra[it].x));
            sA[base +  4] = __uint_as_float(f2tf(ra[it].y));
            sA[base +  8] = __uint_as_float(f2tf(ra[it].z));
            sA[base + 12] = __uint_as_float(f2tf(ra[it].w));
        }
        #pragma unroll
        for (int it = 0; it < 8; it++){
            const int idx = it*256 + t, row = idx >> 3, c4 = idx & 7;
            const int nt = row >> 3, s = c4 >> 1, r = c4 & 1;
            const int lb = (row & 7) * 4;
            const int base = ((nt*NS + s)*32 + lb)*2 + r;
            sB[base    ] = __uint_as_float(f2tf(rb[it].x));
            sB[base + 2] = __uint_as_float(f2tf(rb[it].y));
            sB[base + 4] = __uint_as_float(f2tf(rb[it].z));
            sB[base + 6] = __uint_as_float(f2tf(rb[it].w));
        }
    }
    __syncthreads();

    // ---- main loop ----
    for (int kc = 0; kc < NC; kc++){
        const int buf = kc & 1;
        if (kc + 1 < NC){
            const int k0 = (kc + 1) * BK;
            #pragma unroll
            for (int it = 0; it < 4; it++){
                const int idx = it*256 + t, row = idx >> 3, c4 = idx & 7;
                ra[it] = *(const float4*)(A + (size_t)(m0 + row)*lda + k0 + c4*4);
            }
            #pragma unroll
            for (int it = 0; it < 8; it++){
                const int idx = it*256 + t, row = idx >> 3, c4 = idx & 7;
                rb[it] = *(const float4*)(W + (size_t)(n0 + row)*ldw + k0 + c4*4);
            }
        }
        // compute on buf
        {
            const float* sA = sAb[buf];
            const float* sB = sBb[buf];
            #pragma unroll
            for (int s = 0; s < NS; s++){
                uint32_t afr[4][4], bfr[8][2];
                #pragma unroll
                for (int i = 0; i < 4; i++){
                    const int g = wm*4 + i;
                    float4 v = *(const float4*)(sA + ((g*NS + s)*32 + lane)*4);
                    afr[i][0] = __float_as_uint(v.x);
                    afr[i][1] = __float_as_uint(v.y);
                    afr[i][2] = __float_as_uint(v.z);
                    afr[i][3] = __float_as_uint(v.w);
                }
                #pragma unroll
                for (int j = 0; j < 8; j++){
                    const int nt = wn*8 + j;
                    float2 v = *(const float2*)(sB + ((nt*NS + s)*32 + lane)*2);
                    bfr[j][0] = __float_as_uint(v.x);
                    bfr[j][1] = __float_as_uint(v.y);
                }
                #pragma unroll
                for (int i = 0; i < 4; i++)
                    #pragma unroll
                    for (int j = 0; j < 8; j++)
                        mma8(acc[i][j], afr[i], bfr[j]);
            }
        }
        if (kc + 1 < NC){
            float* sA = sAb[buf ^ 1]; float* sB = sBb[buf ^ 1];
            #pragma unroll
            for (int it = 0; it < 4; it++){
                const int idx = it*256 + t, row = idx >> 3, c4 = idx & 7;
                const int g = row >> 4, s = c4 >> 1;
                const int r = ((c4 & 1) << 1) | ((row >> 3) & 1);
                const int lb = (row & 7) * 4;
                const int base = ((g*NS + s)*32 + lb)*4 + r;
                sA[base     ] = __uint_as_float(f2tf(ra[it].x));
                sA[base +  4] = __uint_as_float(f2tf(ra[it].y));
                sA[base +  8] = __uint_as_float(f2tf(ra[it].z));
                sA[base + 12] = __uint_as_float(f2tf(ra[it].w));
            }
            #pragma unroll
            for (int it = 0; it < 8; it++){
                const int idx = it*256 + t, row = idx >> 3, c4 = idx & 7;
                const int nt = row >> 3, s = c4 >> 1, r = c4 & 1;
                const int lb = (row & 7) * 4;
                const int base = ((nt*NS + s)*32 + lb)*2 + r;
                sB[base    ] = __uint_as_float(f2tf(rb[it].x));
                sB[base + 2] = __uint_as_float(f2tf(rb[it].y));
                sB[base + 4] = __uint_as_float(f2tf(rb[it].z));
                sB[base + 6] = __uint_as_float(f2tf(rb[it].w));
            }
        }
        __syncthreads();
    }

    // ---- epilogue ----
    #pragma unroll
    for (int i = 0; i < 4; i++){
        const int rlo = m0 + wm*64 + i*16 + gid;
        float plo0 = 0.f, plo1 = 0.f, phi0 = 0.f, phi1 = 0.f;
        if (EPI == 2){
            plo0 = __ldg(&pos[(size_t)rlo*2]);     plo1 = __ldg(&pos[(size_t)rlo*2 + 1]);
            phi0 = __ldg(&pos[(size_t)(rlo+8)*2]); phi1 = __ldg(&pos[(size_t)(rlo+8)*2 + 1]);
        }
        #pragma unroll
        for (int j = 0; j < 8; j++){
            const int cb = n0 + wn*64 + j*8 + tig*2;
            if (EPI == 3){
                float s0 = acc[i][j][0] + acc[i][j][2];
                float s1 = acc[i][j][1] + acc[i][j][3];
                s0 += __shfl_xor_sync(0xffffffffu, s0, 4);
                s0 += __shfl_xor_sync(0xffffffffu, s0, 8);
                s0 += __shfl_xor_sync(0xffffffffu, s0, 16);
                s1 += __shfl_xor_sync(0xffffffffu, s1, 4);
                s1 += __shfl_xor_sync(0xffffffffu, s1, 8);
                s1 += __shfl_xor_sync(0xffffffffu, s1, 16);
                if (gid == 0){
                    const int dst = (m0 + wm*64 + i*16) >> 4;
                    float2 o;
                    o.x = s0 * 0.0625f + (HAS_BIAS ? __ldg(&bias[cb])   : 0.f);
                    o.y = s1 * 0.0625f + (HAS_BIAS ? __ldg(&bias[cb+1]) : 0.f);
                    *(float2*)(C + (size_t)dst*256 + cb) = o;
                }
            } else {
                float v00 = acc[i][j][0], v01 = acc[i][j][1];
                float v10 = acc[i][j][2], v11 = acc[i][j][3];
                if (HAS_BIAS){
                    const float b0 = __ldg(&bias[cb]), b1 = __ldg(&bias[cb+1]);
                    v00 += b0; v01 += b1; v10 += b0; v11 += b1;
                }
                if (EPI == 1){
                    v00 = gelu_exact(v00); v01 = gelu_exact(v01);
                    v10 = gelu_exact(v10); v11 = gelu_exact(v11);
                }
                if (EPI == 2){
                    const int o0 = cb, o1 = cb + 1;
                    const float ba0 = __ldg(&bfour[(o0 & 127)*2]), bb0 = __ldg(&bfour[(o0 & 127)*2 + 1]);
                    const float ba1 = __ldg(&bfour[(o1 & 127)*2]), bb1 = __ldg(&bfour[(o1 & 127)*2 + 1]);
                    const float TWO_PI = 6.283185307179586f;
                    float prl0 = TWO_PI*(plo0*ba0 + plo1*bb0);
                    float prl1 = TWO_PI*(plo0*ba1 + plo1*bb1);
                    float prh0 = TWO_PI*(phi0*ba0 + phi1*bb0);
                    float prh1 = TWO_PI*(phi0*ba1 + phi1*bb1);
                    v00 += (o0 < 128) ? cosf(prl0) : sinf(prl0);
                    v01 += (o1 < 128) ? cosf(prl1) : sinf(prl1);
                    v10 += (o0 < 128) ? cosf(prh0) : sinf(prh0);
                    v11 += (o1 < 128) ? cosf(prh1) : sinf(prh1);
                }
                *(float2*)(C + (size_t)rlo*ldc + cb)       = make_float2(v00, v01);
                *(float2*)(C + (size_t)(rlo + 8)*ldc + cb) = make_float2(v10, v11);
            }
        }
    }
}

// ---------------------------------------------------------------------------
extern "C" void kernel_launch(void* const* d_in, const int* in_sizes, int n_in,
                              void* d_out, int out_size)
{
    const float* x        = (const float*)d_in[0];
    const float* mesh_pos = (const float*)d_in[1];
    const int*   me32     = (const int*)  d_in[2];
    const float* ip_w1 = (const float*)d_in[4];
    const float* ip_b1 = (const float*)d_in[5];
    const float* ip_w2 = (const float*)d_in[6];
    const float* ip_b2 = (const float*)d_in[7];
    const float* ip_w3 = (const float*)d_in[8];
    const float* ip_b3 = (const float*)d_in[9];
    const float* bf    = (const float*)d_in[10];
    const float* mw1   = (const float*)d_in[11];
    const float* mb1   = (const float*)d_in[12];
    const float* mw2   = (const float*)d_in[13];
    const float* mb2   = (const float*)d_in[14];
    const float* mw3   = (const float*)d_in[15];
    const float* mb3   = (const float*)d_in[16];
    float* out = (float*)d_out;

    float *bufA, *bufB, *ea, *eb, *m1;
    cudaGetSymbolAddress((void**)&bufA, g_bufA);
    cudaGetSymbolAddress((void**)&bufB, g_bufB);
    cudaGetSymbolAddress((void**)&ea,   g_ea);
    cudaGetSymbolAddress((void**)&eb,   g_eb);
    cudaGetSymbolAddress((void**)&m1,   g_m1);

    cudaFuncSetAttribute(gemm_mma_kernel<256,1,true>,  cudaFuncAttributeMaxDynamicSharedMemorySize, GEMM_SMEM);
    cudaFuncSetAttribute(gemm_mma_kernel<256,2,true>,  cudaFuncAttributeMaxDynamicSharedMemorySize, GEMM_SMEM);
    cudaFuncSetAttribute(gemm_mma_kernel<256,0,false>, cudaFuncAttributeMaxDynamicSharedMemorySize, GEMM_SMEM);
    cudaFuncSetAttribute(gemm_mma_kernel<256,0,true>,  cudaFuncAttributeMaxDynamicSharedMemorySize, GEMM_SMEM);
    cudaFuncSetAttribute(gemm_mma_kernel<512,1,true>,  cudaFuncAttributeMaxDynamicSharedMemorySize, GEMM_SMEM);
    cudaFuncSetAttribute(gemm_mma_kernel<256,3,true>,  cudaFuncAttributeMaxDynamicSharedMemorySize, GEMM_SMEM);

    detect_kernel<<<1, 32>>>(me32);

    // node encoder
    h1_kernel<<<N_NODES/64, 256>>>(x, ip_w1, ip_b1);                         // bufA = h1
    gemm_mma_kernel<256,1,true><<<dim3(N_NODES/BM,1), 256, GEMM_SMEM>>>(
        bufA, 256, ip_w2, 256, ip_b2, bufB, 256, nullptr, nullptr);          // bufB = h2
    gemm_mma_kernel<256,2,true><<<dim3(N_NODES/BM,1), 256, GEMM_SMEM>>>(
        bufB, 256, ip_w3, 256, ip_b3, bufA, 256, mesh_pos, bf);              // bufA = h

    // hoisted edge layer-1 halves
    gemm_mma_kernel<256,0,false><<<dim3(N_NODES/BM,2), 256, GEMM_SMEM>>>(
        bufA, 256, mw1, 512, nullptr, ea, 512, nullptr, nullptr);            // ea = h @ W1a^T
    gemm_mma_kernel<256,0,true><<<dim3(N_DST/BM,2), 256, GEMM_SMEM>>>(
        bufA, 256, mw1 + 256, 512, mb1, eb, 512, nullptr, nullptr);          // eb = h[:16384] @ W1b^T + b1

    // m1 = gelu(ea[src] + eb[dst])
    gather_m1_kernel<<<(N_EDGES*128)/256, 256>>>(me32);

    // edge layers 2,3 (+ fused segment mean)
    gemm_mma_kernel<512,1,true><<<dim3(N_EDGES/BM,1), 256, GEMM_SMEM>>>(
        m1, 512, mw2, 512, mb2, ea, 256, nullptr, nullptr);                  // ea = m2
    gemm_mma_kernel<256,3,true><<<dim3(N_EDGES/BM,1), 256, GEMM_SMEM>>>(
        ea, 256, mw3, 256, mb3, out, 256, nullptr, nullptr);                 // out = mean(m3)
}

// round 4
// speedup vs baseline: 9.3733x; 2.1218x over previous
#include <cuda_runtime.h>
#include <cuda_fp16.h>
#include <math.h>
#include <stdint.h>

#define N_NODES 131072
#define N_DST   16384
#define DEG     16
#define N_EDGES (N_DST*DEG)
#define HID     256

// ---------------- global scratch (device globals: no runtime alloc) --------
__device__ __align__(16) __half g_h1 [(size_t)N_NODES * 256];
__device__ __align__(16) __half g_h2a[(size_t)N_NODES * 256];
__device__ __align__(16) __half g_hh [(size_t)N_NODES * 256];
__device__ __align__(16) float  g_ea [(size_t)N_NODES * 512];
__device__ __align__(16) float  g_eb [(size_t)N_DST   * 512];
__device__ __align__(16) __half g_m2 [(size_t)N_EDGES * 256];
__device__ __align__(16) __half g_w2h [256*256];
__device__ __align__(16) __half g_w3h [256*256];
__device__ __align__(16) __half g_mw1h[512*512];
__device__ __align__(16) __half g_mw2h[256*512];
__device__ __align__(16) __half g_mw3h[256*256];
__device__ int g_is64;

__device__ __forceinline__ float gelu_exact(float x){
    return 0.5f * x * (1.0f + erff(x * 0.70710678118654752f));
}
__device__ __forceinline__ uint32_t smem_u32(const void* p){
    uint32_t a;
    asm("{ .reg .u64 t; cvta.to.shared.u64 t, %1; cvt.u32.u64 %0, t; }" : "=r"(a) : "l"(p));
    return a;
}
__device__ __forceinline__ void mma16(float* c, const uint32_t* a, const uint32_t* b){
    asm volatile("mma.sync.aligned.m16n8k16.row.col.f32.f16.f16.f32 "
        "{%0,%1,%2,%3}, {%4,%5,%6,%7}, {%8,%9}, {%0,%1,%2,%3};"
        : "+f"(c[0]), "+f"(c[1]), "+f"(c[2]), "+f"(c[3])
        : "r"(a[0]), "r"(a[1]), "r"(a[2]), "r"(a[3]), "r"(b[0]), "r"(b[1]));
}
#define CP16(dst, src) \
    asm volatile("cp.async.ca.shared.global [%0], [%1], 16;" :: "r"(dst), "l"(src) : "memory")
#define CP_COMMIT() asm volatile("cp.async.commit_group;" ::: "memory")
#define CP_WAIT2()  asm volatile("cp.async.wait_group 2;"  ::: "memory")

// ---------------------------------------------------------------------------
__global__ void detect_kernel(const int* __restrict__ me32){
    if (threadIdx.x == 0 && blockIdx.x == 0) g_is64 = (me32[32] != 1) ? 1 : 0;
}
__global__ void f2h_kernel(const float* __restrict__ s, __half* __restrict__ d, int n){
    int i = blockIdx.x*256 + threadIdx.x;
    if (i < n) d[i] = __float2half_rn(s[i]);
}

// h1 = gelu(x @ W1^T + b1), K=3: fp32 math, fp16 store.
__global__ __launch_bounds__(256)
void h1_kernel(const float* __restrict__ x,
               const float* __restrict__ w1, const float* __restrict__ b1){
    __shared__ float sx[64*3];
    const int t  = threadIdx.x;
    const int n0 = blockIdx.x * 64;
    for (int i = t; i < 64*3; i += 256) sx[i] = x[(size_t)n0*3 + i];
    __syncthreads();
    const float wa = w1[t*3+0], wb = w1[t*3+1], wc = w1[t*3+2], bb = b1[t];
    for (int n = 0; n < 64; n++){
        float v = fmaf(wa, sx[n*3+0], fmaf(wb, sx[n*3+1], fmaf(wc, sx[n*3+2], bb)));
        g_h1[(size_t)(n0+n)*256 + t] = __float2half_rn(gelu_exact(v));
    }
}

// ---------------------------------------------------------------------------
// fp16 mma.sync GEMM: C[M x Ntot] = epi(A[M x K] @ W[Ntot x K]^T + bias)
// Block 128x256, BK=32, 512 threads = 16 warps (4x4), warp tile 32x64.
// 4-stage cp.async pipeline, XOR-swizzled row-major smem (64B rows).
// FUSED: A = gelu(g_ea[src] + g_eb[dst]) computed on the fly (m2 layer).
// EPI: 0=fp32 store(+bias), 1=gelu->fp16, 2=+fourier->fp16, 3=segment-mean fp32.
// ---------------------------------------------------------------------------
#define GEMM_SMEM (96*1024)

template<int K, int EPI, bool HAS_BIAS, bool FUSED>
__global__ __launch_bounds__(512, 1)
void gemm16(const __half* __restrict__ A, int lda,
            const __half* __restrict__ W, int ldw,
            const float* __restrict__ bias,
            void* __restrict__ Cout, int ldc,
            const float* __restrict__ pos,
            const float* __restrict__ bfour,
            const int* __restrict__ me32)
{
    extern __shared__ char smem[];
    __shared__ int sSrc[128], sDst[128];
    const int t    = threadIdx.x;
    const int lane = t & 31;
    const int w    = t >> 5;
    const int wm   = w >> 2, wn = w & 3;
    const int gid  = lane >> 2, tig = lane & 3;
    const int m0   = blockIdx.x * 128;
    const int n0   = blockIdx.y * 256;
    const uint32_t sb = smem_u32(smem);

    if (FUSED){
        if (t < 128){
            const int e = m0 + t; int s, d;
            if (g_is64){ d = me32[4*e]; s = me32[4*e+2]; }
            else       { d = me32[2*e]; s = me32[2*e+1]; }
            sSrc[t] = s; sDst[t] = d;
        }
        __syncthreads();
    }

    float acc[2][8][4];
    #pragma unroll
    for (int i = 0; i < 2; i++)
        #pragma unroll
        for (int j = 0; j < 8; j++)
            #pragma unroll
            for (int r = 0; r < 4; r++) acc[i][j][r] = 0.f;

    constexpr int NC = K / 32;

    auto produce = [&](int kc){
        const int st = kc & 3;
        const int r = t >> 2, c = t & 3;
        if (!FUSED){
            uint32_t dst = sb + st*8192 + r*64 + (uint32_t)((c ^ ((r>>1)&3)) << 4);
            CP16(dst, (const void*)(A + (size_t)(m0 + r)*lda + kc*32 + c*8));
        } else {
            const int k0 = kc*32 + c*8;
            const float* pa = g_ea + (size_t)sSrc[r]*512 + k0;
            const float* pb = g_eb + (size_t)sDst[r]*512 + k0;
            float4 a0 = *(const float4*)pa, a1 = *(const float4*)(pa + 4);
            float4 b0 = *(const float4*)pb, b1 = *(const float4*)(pb + 4);
            __half2 h0 = __floats2half2_rn(gelu_exact(a0.x+b0.x), gelu_exact(a0.y+b0.y));
            __half2 h1 = __floats2half2_rn(gelu_exact(a0.z+b0.z), gelu_exact(a0.w+b0.w));
            __half2 h2 = __floats2half2_rn(gelu_exact(a1.x+b1.x), gelu_exact(a1.y+b1.y));
            __half2 h3 = __floats2half2_rn(gelu_exact(a1.z+b1.z), gelu_exact(a1.w+b1.w));
            uint4 pk;
            pk.x = *reinterpret_cast<uint32_t*>(&h0);
            pk.y = *reinterpret_cast<uint32_t*>(&h1);
            pk.z = *reinterpret_cast<uint32_t*>(&h2);
            pk.w = *reinterpret_cast<uint32_t*>(&h3);
            *(uint4*)(smem + st*8192 + r*64 + ((c ^ ((r>>1)&3)) << 4)) = pk;
        }
        #pragma unroll
        for (int it = 0; it < 2; it++){
            const int idx = it*512 + t, rr = idx >> 2, cc = idx & 3;
            uint32_t dst = sb + 32768 + st*16384 + rr*64 + (uint32_t)((cc ^ ((rr>>1)&3)) << 4);
            CP16(dst, (const void*)(W + (size_t)(n0 + rr)*ldw + kc*32 + cc*8));
        }
        CP_COMMIT();
    };

    produce(0); produce(1); produce(2);

    for (int kc = 0; kc < NC; kc++){
        CP_WAIT2();
        __syncthreads();
        const char* bA = smem + (kc & 3)*8192;
        const char* bB = smem + 32768 + (kc & 3)*16384;
        #pragma unroll
        for (int s = 0; s < 2; s++){
            uint32_t afr[2][4], bfr[8][2];
            #pragma unroll
            for (int mi = 0; mi < 2; mi++){
                const int r0 = wm*32 + mi*16 + gid, r1 = r0 + 8;
                const int sw0 = (r0>>1)&3, sw1 = (r1>>1)&3;
                afr[mi][0] = *(const uint32_t*)(bA + r0*64 + (((2*s  ) ^ sw0) << 4) + 4*tig);
                afr[mi][1] = *(const uint32_t*)(bA + r1*64 + (((2*s  ) ^ sw1) << 4) + 4*tig);
                afr[mi][2] = *(const uint32_t*)(bA + r0*64 + (((2*s+1) ^ sw0) << 4) + 4*tig);
                afr[mi][3] = *(const uint32_t*)(bA + r1*64 + (((2*s+1) ^ sw1) << 4) + 4*tig);
            }
            #pragma unroll
            for (int nj = 0; nj < 8; nj++){
                const int rn = wn*64 + nj*8 + gid;
                const int swn = (rn>>1)&3;
                bfr[nj][0] = *(const uint32_t*)(bB + rn*64 + (((2*s  ) ^ swn) << 4) + 4*tig);
                bfr[nj][1] = *(const uint32_t*)(bB + rn*64 + (((2*s+1) ^ swn) << 4) + 4*tig);
            }
            #pragma unroll
            for (int mi = 0; mi < 2; mi++)
                #pragma unroll
                for (int nj = 0; nj < 8; nj++)
                    mma16(acc[mi][nj], afr[mi], bfr[nj]);
        }
        if (kc + 3 < NC) produce(kc + 3);
    }

    // ---- epilogue ----
    #pragma unroll
    for (int mi = 0; mi < 2; mi++){
        const int r0 = m0 + wm*32 + mi*16 + gid;
        const int r1 = r0 + 8;
        float p00 = 0.f, p01 = 0.f, p10 = 0.f, p11 = 0.f;
        if (EPI == 2){
            p00 = pos[(size_t)r0*2]; p01 = pos[(size_t)r0*2 + 1];
            p10 = pos[(size_t)r1*2]; p11 = pos[(size_t)r1*2 + 1];
        }
        #pragma unroll
        for (int nj = 0; nj < 8; nj++){
            const int cb = n0 + wn*64 + nj*8 + 2*tig;
            float v0 = acc[mi][nj][0], v1 = acc[mi][nj][1];
            float v2 = acc[mi][nj][2], v3 = acc[mi][nj][3];
            if (EPI == 3){
                float s0 = v0 + v2, s1 = v1 + v3;
                s0 += __shfl_xor_sync(0xffffffffu, s0, 4);
                s0 += __shfl_xor_sync(0xffffffffu, s0, 8);
                s0 += __shfl_xor_sync(0xffffffffu, s0, 16);
                s1 += __shfl_xor_sync(0xffffffffu, s1, 4);
                s1 += __shfl_xor_sync(0xffffffffu, s1, 8);
                s1 += __shfl_xor_sync(0xffffffffu, s1, 16);
                if (lane < 4){
                    const int dst = (m0 + wm*32 + mi*16) >> 4;
                    float2 o;
                    o.x = s0 * 0.0625f + (HAS_BIAS ? bias[cb]   : 0.f);
                    o.y = s1 * 0.0625f + (HAS_BIAS ? bias[cb+1] : 0.f);
                    *(float2*)((float*)Cout + (size_t)dst*ldc + cb) = o;
                }
            } else {
                if (HAS_BIAS){
                    const float b0 = bias[cb], b1 = bias[cb+1];
                    v0 += b0; v1 += b1; v2 += b0; v3 += b1;
                }
                if (EPI == 1){
                    v0 = gelu_exact(v0); v1 = gelu_exact(v1);
                    v2 = gelu_exact(v2); v3 = gelu_exact(v3);
                }
                if (EPI == 2){
                    const int o0 = cb & 255, o1 = (cb+1) & 255;
                    const float ba0 = bfour[(o0 & 127)*2], bb0 = bfour[(o0 & 127)*2 + 1];
                    const float ba1 = bfour[(o1 & 127)*2], bb1 = bfour[(o1 & 127)*2 + 1];
                    const float TP = 6.283185307179586f;
                    float pl0 = TP*(p00*ba0 + p01*bb0), pl1 = TP*(p00*ba1 + p01*bb1);
                    float ph0 = TP*(p10*ba0 + p11*bb0), ph1 = TP*(p10*ba1 + p11*bb1);
                    v0 += (o0 < 128) ? __cosf(pl0) : __sinf(pl0);
                    v1 += (o1 < 128) ? __cosf(pl1) : __sinf(pl1);
                    v2 += (o0 < 128) ? __cosf(ph0) : __sinf(ph0);
                    v3 += (o1 < 128) ? __cosf(ph1) : __sinf(ph1);
                }
                if (EPI == 0){
                    float* C = (float*)Cout;
                    *(float2*)(C + (size_t)r0*ldc + cb) = make_float2(v0, v1);
                    *(float2*)(C + (size_t)r1*ldc + cb) = make_float2(v2, v3);
                } else {
                    __half* C = (__half*)Cout;
                    *(__half2*)(C + (size_t)r0*ldc + cb) = __floats2half2_rn(v0, v1);
                    *(__half2*)(C + (size_t)r1*ldc + cb) = __floats2half2_rn(v2, v3);
                }
            }
        }
    }
}

// ---------------------------------------------------------------------------
extern "C" void kernel_launch(void* const* d_in, const int* in_sizes, int n_in,
                              void* d_out, int out_size)
{
    const float* x        = (const float*)d_in[0];
    const float* mesh_pos = (const float*)d_in[1];
    const int*   me32     = (const int*)  d_in[2];
    const float* ip_w1 = (const float*)d_in[4];
    const float* ip_b1 = (const float*)d_in[5];
    const float* ip_w2 = (const float*)d_in[6];
    const float* ip_b2 = (const float*)d_in[7];
    const float* ip_w3 = (const float*)d_in[8];
    const float* ip_b3 = (const float*)d_in[9];
    const float* bf    = (const float*)d_in[10];
    const float* mw1   = (const float*)d_in[11];
    const float* mb1   = (const float*)d_in[12];
    const float* mw2   = (const float*)d_in[13];
    const float* mb2   = (const float*)d_in[14];
    const float* mw3   = (const float*)d_in[15];
    const float* mb3   = (const float*)d_in[16];
    float* out = (float*)d_out;

    __half *h1p, *h2p, *hhp, *m2p, *w2h, *w3h, *mw1h, *mw2h, *mw3h;
    float  *eap, *ebp;
    cudaGetSymbolAddress((void**)&h1p,  g_h1);
    cudaGetSymbolAddress((void**)&h2p,  g_h2a);
    cudaGetSymbolAddress((void**)&hhp,  g_hh);
    cudaGetSymbolAddress((void**)&eap,  g_ea);
    cudaGetSymbolAddress((void**)&ebp,  g_eb);
    cudaGetSymbolAddress((void**)&m2p,  g_m2);
    cudaGetSymbolAddress((void**)&w2h,  g_w2h);
    cudaGetSymbolAddress((void**)&w3h,  g_w3h);
    cudaGetSymbolAddress((void**)&mw1h, g_mw1h);
    cudaGetSymbolAddress((void**)&mw2h, g_mw2h);
    cudaGetSymbolAddress((void**)&mw3h, g_mw3h);

    cudaFuncSetAttribute(gemm16<256,1,true ,false>, cudaFuncAttributeMaxDynamicSharedMemorySize, GEMM_SMEM);
    cudaFuncSetAttribute(gemm16<256,2,true ,false>, cudaFuncAttributeMaxDynamicSharedMemorySize, GEMM_SMEM);
    cudaFuncSetAttribute(gemm16<256,0,false,false>, cudaFuncAttributeMaxDynamicSharedMemorySize, GEMM_SMEM);
    cudaFuncSetAttribute(gemm16<256,0,true ,false>, cudaFuncAttributeMaxDynamicSharedMemorySize, GEMM_SMEM);
    cudaFuncSetAttribute(gemm16<512,1,true ,true >, cudaFuncAttributeMaxDynamicSharedMemorySize, GEMM_SMEM);
    cudaFuncSetAttribute(gemm16<256,3,true ,false>, cudaFuncAttributeMaxDynamicSharedMemorySize, GEMM_SMEM);

    detect_kernel<<<1, 32>>>(me32);

    // weight fp16 prep
    f2h_kernel<<<(256*256+255)/256, 256>>>(ip_w2, w2h, 256*256);
    f2h_kernel<<<(256*256+255)/256, 256>>>(ip_w3, w3h, 256*256);
    f2h_kernel<<<(512*512+255)/256, 256>>>(mw1,  mw1h, 512*512);
    f2h_kernel<<<(256*512+255)/256, 256>>>(mw2,  mw2h, 256*512);
    f2h_kernel<<<(256*256+255)/256, 256>>>(mw3,  mw3h, 256*256);

    // node encoder
    h1_kernel<<<N_NODES/64, 256>>>(x, ip_w1, ip_b1);
    gemm16<256,1,true ,false><<<dim3(N_NODES/128,1), 512, GEMM_SMEM>>>(
        h1p, 256, w2h, 256, ip_b2, h2p, 256, nullptr, nullptr, nullptr);
    gemm16<256,2,true ,false><<<dim3(N_NODES/128,1), 512, GEMM_SMEM>>>(
        h2p, 256, w3h, 256, ip_b3, hhp, 256, mesh_pos, bf, nullptr);

    // hoisted edge layer-1 halves (fp32 outputs)
    gemm16<256,0,false,false><<<dim3(N_NODES/128,2), 512, GEMM_SMEM>>>(
        hhp, 256, mw1h, 512, nullptr, eap, 512, nullptr, nullptr, nullptr);
    gemm16<256,0,true ,false><<<dim3(N_DST/128,2), 512, GEMM_SMEM>>>(
        hhp, 256, mw1h + 256, 512, mb1, ebp, 512, nullptr, nullptr, nullptr);

    // edge layer 2 (fused gather+gelu producer), then layer 3 + segment mean
    gemm16<512,1,true ,true ><<<dim3(N_EDGES/128,1), 512, GEMM_SMEM>>>(
        nullptr, 0, mw2h, 512, mb2, m2p, 256, nullptr, nullptr, me32);
    gemm16<256,3,true ,false><<<dim3(N_EDGES/128,1), 512, GEMM_SMEM>>>(
        m2p, 256, mw3h, 256, mb3, out, 256, nullptr, nullptr, nullptr);
}

// round 5
// speedup vs baseline: 9.8555x; 1.0514x over previous
#include <cuda_runtime.h>
#include <cuda_fp16.h>
#include <math.h>
#include <stdint.h>

#define N_NODES 131072
#define N_DST   16384
#define DEG     16
#define N_EDGES (N_DST*DEG)
#define HID     256

// ---------------- global scratch (device globals: no runtime alloc) --------
__device__ __align__(16) __half g_h1 [(size_t)N_NODES * 256];
__device__ __align__(16) __half g_h2a[(size_t)N_NODES * 256];
__device__ __align__(16) __half g_hh [(size_t)N_NODES * 256];
__device__ __align__(16) __half g_eaH[(size_t)N_NODES * 512];
__device__ __align__(16) float  g_eb [(size_t)N_DST   * 512];
__device__ __align__(16) __half g_w2h [256*256];
__device__ __align__(16) __half g_w3h [256*256];
__device__ __align__(16) __half g_mw1h[512*512];
__device__ __align__(16) __half g_mw2h[256*512];
__device__ __align__(16) __half g_mw3h[256*256];
__device__ int g_is64;

__device__ __forceinline__ float gelu_exact(float x){
    return 0.5f * x * (1.0f + erff(x * 0.70710678118654752f));
}
__device__ __forceinline__ uint32_t smem_u32(const void* p){
    uint32_t a;
    asm("{ .reg .u64 t; cvta.to.shared.u64 t, %1; cvt.u32.u64 %0, t; }" : "=r"(a) : "l"(p));
    return a;
}
__device__ __forceinline__ void mma16(float* c, const uint32_t* a, const uint32_t* b){
    asm volatile("mma.sync.aligned.m16n8k16.row.col.f32.f16.f16.f32 "
        "{%0,%1,%2,%3}, {%4,%5,%6,%7}, {%8,%9}, {%0,%1,%2,%3};"
        : "+f"(c[0]), "+f"(c[1]), "+f"(c[2]), "+f"(c[3])
        : "r"(a[0]), "r"(a[1]), "r"(a[2]), "r"(a[3]), "r"(b[0]), "r"(b[1]));
}
#define CP16(dst, src) \
    asm volatile("cp.async.ca.shared.global [%0], [%1], 16;" :: "r"(dst), "l"(src) : "memory")
#define CP_COMMIT() asm volatile("cp.async.commit_group;" ::: "memory")
#define CP_WAIT2()  asm volatile("cp.async.wait_group 2;"  ::: "memory")
#define CP_WAIT1()  asm volatile("cp.async.wait_group 1;"  ::: "memory")

// ---------------------------------------------------------------------------
__global__ void detect_kernel(const int* __restrict__ me32){
    if (threadIdx.x == 0 && blockIdx.x == 0) g_is64 = (me32[32] != 1) ? 1 : 0;
}
__global__ void f2h_kernel(const float* __restrict__ s, __half* __restrict__ d, int n){
    int i = blockIdx.x*256 + threadIdx.x;
    if (i < n) d[i] = __float2half_rn(s[i]);
}

// h1 = gelu(x @ W1^T + b1), K=3: fp32 math, fp16 store.
__global__ __launch_bounds__(256)
void h1_kernel(const float* __restrict__ x,
               const float* __restrict__ w1, const float* __restrict__ b1){
    __shared__ float sx[64*3];
    const int t  = threadIdx.x;
    const int n0 = blockIdx.x * 64;
    for (int i = t; i < 64*3; i += 256) sx[i] = x[(size_t)n0*3 + i];
    __syncthreads();
    const float wa = w1[t*3+0], wb = w1[t*3+1], wc = w1[t*3+2], bb = b1[t];
    for (int n = 0; n < 64; n++){
        float v = fmaf(wa, sx[n*3+0], fmaf(wb, sx[n*3+1], fmaf(wc, sx[n*3+2], bb)));
        g_h1[(size_t)(n0+n)*256 + t] = __float2half_rn(gelu_exact(v));
    }
}

// ---------------------------------------------------------------------------
// fp16 mma.sync GEMM: C[M x Ntot] = epi(A[M x K] @ W[Ntot x K]^T + bias)
// Block 128x256, BK=32, 512 threads = 16 warps (4x4), warp tile 32x64.
// 4-stage cp.async pipeline, XOR-swizzled row-major smem (64B rows).
// EPI: 0=fp32 store(+bias), 1=gelu->fp16, 2=+fourier->fp16, 4=plain fp16.
// ---------------------------------------------------------------------------
#define GEMM_SMEM (96*1024)

template<int K, int EPI, bool HAS_BIAS>
__global__ __launch_bounds__(512, 1)
void gemm16(const __half* __restrict__ A, int lda,
            const __half* __restrict__ W, int ldw,
            const float* __restrict__ bias,
            void* __restrict__ Cout, int ldc,
            const float* __restrict__ pos,
            const float* __restrict__ bfour)
{
    extern __shared__ char smem[];
    const int t    = threadIdx.x;
    const int lane = t & 31;
    const int w    = t >> 5;
    const int wm   = w >> 2, wn = w & 3;
    const int gid  = lane >> 2, tig = lane & 3;
    const int m0   = blockIdx.x * 128;
    const int n0   = blockIdx.y * 256;
    const uint32_t sb = smem_u32(smem);

    float acc[2][8][4];
    #pragma unroll
    for (int i = 0; i < 2; i++)
        #pragma unroll
        for (int j = 0; j < 8; j++)
            #pragma unroll
            for (int r = 0; r < 4; r++) acc[i][j][r] = 0.f;

    constexpr int NC = K / 32;

    auto produce = [&](int kc){
        const int st = kc & 3;
        const int r = t >> 2, c = t & 3;
        uint32_t dst = sb + st*8192 + r*64 + (uint32_t)((c ^ ((r>>1)&3)) << 4);
        CP16(dst, (const void*)(A + (size_t)(m0 + r)*lda + kc*32 + c*8));
        #pragma unroll
        for (int it = 0; it < 2; it++){
            const int idx = it*512 + t, rr = idx >> 2, cc = idx & 3;
            uint32_t db = sb + 32768 + st*16384 + rr*64 + (uint32_t)((cc ^ ((rr>>1)&3)) << 4);
            CP16(db, (const void*)(W + (size_t)(n0 + rr)*ldw + kc*32 + cc*8));
        }
        CP_COMMIT();
    };

    produce(0); produce(1); produce(2);

    for (int kc = 0; kc < NC; kc++){
        CP_WAIT2();
        __syncthreads();
        const char* bA = smem + (kc & 3)*8192;
        const char* bB = smem + 32768 + (kc & 3)*16384;
        #pragma unroll
        for (int s = 0; s < 2; s++){
            uint32_t afr[2][4], bfr[8][2];
            #pragma unroll
            for (int mi = 0; mi < 2; mi++){
                const int r0 = wm*32 + mi*16 + gid, r1 = r0 + 8;
                const int sw0 = (r0>>1)&3, sw1 = (r1>>1)&3;
                afr[mi][0] = *(const uint32_t*)(bA + r0*64 + (((2*s  ) ^ sw0) << 4) + 4*tig);
                afr[mi][1] = *(const uint32_t*)(bA + r1*64 + (((2*s  ) ^ sw1) << 4) + 4*tig);
                afr[mi][2] = *(const uint32_t*)(bA + r0*64 + (((2*s+1) ^ sw0) << 4) + 4*tig);
                afr[mi][3] = *(const uint32_t*)(bA + r1*64 + (((2*s+1) ^ sw1) << 4) + 4*tig);
            }
            #pragma unroll
            for (int nj = 0; nj < 8; nj++){
                const int rn = wn*64 + nj*8 + gid;
                const int swn = (rn>>1)&3;
                bfr[nj][0] = *(const uint32_t*)(bB + rn*64 + (((2*s  ) ^ swn) << 4) + 4*tig);
                bfr[nj][1] = *(const uint32_t*)(bB + rn*64 + (((2*s+1) ^ swn) << 4) + 4*tig);
            }
            #pragma unroll
            for (int mi = 0; mi < 2; mi++)
                #pragma unroll
                for (int nj = 0; nj < 8; nj++)
                    mma16(acc[mi][nj], afr[mi], bfr[nj]);
        }
        if (kc + 3 < NC) produce(kc + 3); else CP_COMMIT();
    }

    // ---- epilogue ----
    #pragma unroll
    for (int mi = 0; mi < 2; mi++){
        const int r0 = m0 + wm*32 + mi*16 + gid;
        const int r1 = r0 + 8;
        float p00 = 0.f, p01 = 0.f, p10 = 0.f, p11 = 0.f;
        if (EPI == 2){
            p00 = pos[(size_t)r0*2]; p01 = pos[(size_t)r0*2 + 1];
            p10 = pos[(size_t)r1*2]; p11 = pos[(size_t)r1*2 + 1];
        }
        #pragma unroll
        for (int nj = 0; nj < 8; nj++){
            const int cb = n0 + wn*64 + nj*8 + 2*tig;
            float v0 = acc[mi][nj][0], v1 = acc[mi][nj][1];
            float v2 = acc[mi][nj][2], v3 = acc[mi][nj][3];
            if (HAS_BIAS){
                const float b0 = bias[cb], b1 = bias[cb+1];
                v0 += b0; v1 += b1; v2 += b0; v3 += b1;
            }
            if (EPI == 1){
                v0 = gelu_exact(v0); v1 = gelu_exact(v1);
                v2 = gelu_exact(v2); v3 = gelu_exact(v3);
            }
            if (EPI == 2){
                const int o0 = cb & 255, o1 = (cb+1) & 255;
                const float ba0 = bfour[(o0 & 127)*2], bb0 = bfour[(o0 & 127)*2 + 1];
                const float ba1 = bfour[(o1 & 127)*2], bb1 = bfour[(o1 & 127)*2 + 1];
                const float TP = 6.283185307179586f;
                float pl0 = TP*(p00*ba0 + p01*bb0), pl1 = TP*(p00*ba1 + p01*bb1);
                float ph0 = TP*(p10*ba0 + p11*bb0), ph1 = TP*(p10*ba1 + p11*bb1);
                v0 += (o0 < 128) ? __cosf(pl0) : __sinf(pl0);
                v1 += (o1 < 128) ? __cosf(pl1) : __sinf(pl1);
                v2 += (o0 < 128) ? __cosf(ph0) : __sinf(ph0);
                v3 += (o1 < 128) ? __cosf(ph1) : __sinf(ph1);
            }
            if (EPI == 0){
                float* C = (float*)Cout;
                *(float2*)(C + (size_t)r0*ldc + cb) = make_float2(v0, v1);
                *(float2*)(C + (size_t)r1*ldc + cb) = make_float2(v2, v3);
            } else {
                __half* C = (__half*)Cout;
                *(__half2*)(C + (size_t)r0*ldc + cb) = __floats2half2_rn(v0, v1);
                *(__half2*)(C + (size_t)r1*ldc + cb) = __floats2half2_rn(v2, v3);
            }
        }
    }
}

// ---------------------------------------------------------------------------
// Fused edge kernel: per block of 128 edges (= 8 dsts):
//   phase 1: m2 = gelu([gelu(ea[src]+eb[dst])] @ W2^T + b2)   (K=512)  -> SMEM
//   phase 2: m3 = m2 @ W3^T + b3 ; out[dst] = mean_16(m3)     (K=256)
// SMEM: [0,32KB) 4x8KB A stages (ph1) then 2x16KB W3 stages (ph2);
//       [32KB,96KB) 4x16KB W2 stages (ph1) then m2 128x512B (ph2).
// ---------------------------------------------------------------------------
__global__ __launch_bounds__(512, 1)
void edge_fused(const __half* __restrict__ eaH, const float* __restrict__ ebF,
                const __half* __restrict__ W2, const float* __restrict__ b2,
                const __half* __restrict__ W3, const float* __restrict__ b3,
                float* __restrict__ out, const int* __restrict__ me32)
{
    extern __shared__ char smem[];
    __shared__ int sSrc[128], sDst[128];
    const int t    = threadIdx.x;
    const int lane = t & 31;
    const int w    = t >> 5;
    const int wm   = w >> 2, wn = w & 3;
    const int gid  = lane >> 2, tig = lane & 3;
    const int m0   = blockIdx.x * 128;
    const uint32_t sb = smem_u32(smem);

    if (t < 128){
        const int e = m0 + t; int s, d;
        if (g_is64){ d = me32[4*e]; s = me32[4*e+2]; }
        else       { d = me32[2*e]; s = me32[2*e+1]; }
        sSrc[t] = s; sDst[t] = d;
    }
    __syncthreads();

    float acc[2][8][4];
    #pragma unroll
    for (int i = 0; i < 2; i++)
        #pragma unroll
        for (int j = 0; j < 8; j++)
            #pragma unroll
            for (int r = 0; r < 4; r++) acc[i][j][r] = 0.f;

    // ---- phase 1 producer: A = gelu(ea[src]+eb[dst]) (STS), B = W2 (cp.async)
    auto produce1 = [&](int kc){
        const int st = kc & 3;
        const int r = t >> 2, c = t & 3;
        const int k0 = kc*32 + c*8;
        uint4 av = *(const uint4*)(eaH + (size_t)sSrc[r]*512 + k0);
        const float* pb = ebF + (size_t)sDst[r]*512 + k0;
        float4 e0 = *(const float4*)pb, e1 = *(const float4*)(pb + 4);
        const __half2* ah = (const __half2*)&av;
        float2 f0 = __half22float2(ah[0]), f1 = __half22float2(ah[1]);
        float2 f2 = __half22float2(ah[2]), f3 = __half22float2(ah[3]);
        __half2 h0 = __floats2half2_rn(gelu_exact(f0.x+e0.x), gelu_exact(f0.y+e0.y));
        __half2 h1 = __floats2half2_rn(gelu_exact(f1.x+e0.z), gelu_exact(f1.y+e0.w));
        __half2 h2 = __floats2half2_rn(gelu_exact(f2.x+e1.x), gelu_exact(f2.y+e1.y));
        __half2 h3 = __floats2half2_rn(gelu_exact(f3.x+e1.z), gelu_exact(f3.y+e1.w));
        uint4 pk;
        pk.x = *reinterpret_cast<uint32_t*>(&h0);
        pk.y = *reinterpret_cast<uint32_t*>(&h1);
        pk.z = *reinterpret_cast<uint32_t*>(&h2);
        pk.w = *reinterpret_cast<uint32_t*>(&h3);
        *(uint4*)(smem + st*8192 + r*64 + ((c ^ ((r>>1)&3)) << 4)) = pk;
        #pragma unroll
        for (int it = 0; it < 2; it++){
            const int idx = it*512 + t, rr = idx >> 2, cc = idx & 3;
            uint32_t db = sb + 32768 + st*16384 + rr*64 + (uint32_t)((cc ^ ((rr>>1)&3)) << 4);
            CP16(db, (const void*)(W2 + (size_t)rr*512 + kc*32 + cc*8));
        }
        CP_COMMIT();
    };

    produce1(0); produce1(1); produce1(2);

    for (int kc = 0; kc < 16; kc++){
        CP_WAIT2();
        __syncthreads();
        const char* bA = smem + (kc & 3)*8192;
        const char* bB = smem + 32768 + (kc & 3)*16384;
        #pragma unroll
        for (int s = 0; s < 2; s++){
            uint32_t afr[2][4], bfr[8][2];
            #pragma unroll
            for (int mi = 0; mi < 2; mi++){
                const int r0 = wm*32 + mi*16 + gid, r1 = r0 + 8;
                const int sw0 = (r0>>1)&3, sw1 = (r1>>1)&3;
                afr[mi][0] = *(const uint32_t*)(bA + r0*64 + (((2*s  ) ^ sw0) << 4) + 4*tig);
                afr[mi][1] = *(const uint32_t*)(bA + r1*64 + (((2*s  ) ^ sw1) << 4) + 4*tig);
                afr[mi][2] = *(const uint32_t*)(bA + r0*64 + (((2*s+1) ^ sw0) << 4) + 4*tig);
                afr[mi][3] = *(const uint32_t*)(bA + r1*64 + (((2*s+1) ^ sw1) << 4) + 4*tig);
            }
            #pragma unroll
            for (int nj = 0; nj < 8; nj++){
                const int rn = wn*64 + nj*8 + gid;
                const int swn = (rn>>1)&3;
                bfr[nj][0] = *(const uint32_t*)(bB + rn*64 + (((2*s  ) ^ swn) << 4) + 4*tig);
                bfr[nj][1] = *(const uint32_t*)(bB + rn*64 + (((2*s+1) ^ swn) << 4) + 4*tig);
            }
            #pragma unroll
            for (int mi = 0; mi < 2; mi++)
                #pragma unroll
                for (int nj = 0; nj < 8; nj++)
                    mma16(acc[mi][nj], afr[mi], bfr[nj]);
        }
        if (kc + 3 < 16) produce1(kc + 3); else CP_COMMIT();
    }

    __syncthreads();   // everyone done with phase-1 tiles

    // ---- phase 2 W3 producer into [0,32KB), 2 stages
    auto produce2 = [&](int kc){
        const int st = kc & 1;
        #pragma unroll
        for (int it = 0; it < 2; it++){
            const int idx = it*512 + t, rr = idx >> 2, cc = idx & 3;
            uint32_t db = sb + st*16384 + rr*64 + (uint32_t)((cc ^ ((rr>>1)&3)) << 4);
            CP16(db, (const void*)(W3 + (size_t)rr*256 + kc*32 + cc*8));
        }
        CP_COMMIT();
    };
    produce2(0);

    // ---- epilogue-1: m2 = gelu(acc + b2) -> fp16 SMEM at [32KB, 96KB)
    // maddr(r, cb): 512B rows, 16B-block index (cb>>3) ^ (r&7), inner 4*tig
    #pragma unroll
    for (int mi = 0; mi < 2; mi++){
        const int lr0 = wm*32 + mi*16 + gid;
        const int lr1 = lr0 + 8;
        #pragma unroll
        for (int nj = 0; nj < 8; nj++){
            const int cb = wn*64 + nj*8 + 2*tig;
            const float b0 = b2[cb], b1 = b2[cb+1];
            __half2 lo = __floats2half2_rn(gelu_exact(acc[mi][nj][0] + b0),
                                           gelu_exact(acc[mi][nj][1] + b1));
            __half2 hi = __floats2half2_rn(gelu_exact(acc[mi][nj][2] + b0),
                                           gelu_exact(acc[mi][nj][3] + b1));
            const int blk = cb >> 3;
            *(__half2*)(smem + 32768 + lr0*512 + ((blk ^ (lr0 & 7)) << 4) + 4*tig) = lo;
            *(__half2*)(smem + 32768 + lr1*512 + ((blk ^ (lr1 & 7)) << 4) + 4*tig) = hi;
            acc[mi][nj][0] = 0.f; acc[mi][nj][1] = 0.f;
            acc[mi][nj][2] = 0.f; acc[mi][nj][3] = 0.f;
        }
    }

    // ---- phase 2 main loop (K=256, 8 chunks)
    for (int kc = 0; kc < 8; kc++){
        __syncthreads();                 // prev compute done; m2 visible (kc=0)
        if (kc + 1 < 8) produce2(kc + 1); else CP_COMMIT();
        CP_WAIT1();
        __syncthreads();
        const char* bA = smem + 32768;   // m2, 512B rows
        const char* bB = smem + (kc & 1)*16384;
        #pragma unroll
        for (int s = 0; s < 2; s++){
            uint32_t afr[2][4], bfr[8][2];
            #pragma unroll
            for (int mi = 0; mi < 2; mi++){
                const int r0 = wm*32 + mi*16 + gid, r1 = r0 + 8;
                const int b0a = kc*4 + 2*s, b1a = kc*4 + 2*s + 1;
                afr[mi][0] = *(const uint32_t*)(bA + r0*512 + ((b0a ^ (r0&7)) << 4) + 4*tig);
                afr[mi][1] = *(const uint32_t*)(bA + r1*512 + ((b0a ^ (r1&7)) << 4) + 4*tig);
                afr[mi][2] = *(const uint32_t*)(bA + r0*512 + ((b1a ^ (r0&7)) << 4) + 4*tig);
                afr[mi][3] = *(const uint32_t*)(bA + r1*512 + ((b1a ^ (r1&7)) << 4) + 4*tig);
            }
            #pragma unroll
            for (int nj = 0; nj < 8; nj++){
                const int rn = wn*64 + nj*8 + gid;
                const int swn = (rn>>1)&3;
                bfr[nj][0] = *(const uint32_t*)(bB + rn*64 + (((2*s  ) ^ swn) << 4) + 4*tig);
                bfr[nj][1] = *(const uint32_t*)(bB + rn*64 + (((2*s+1) ^ swn) << 4) + 4*tig);
            }
            #pragma unroll
            for (int mi = 0; mi < 2; mi++)
                #pragma unroll
                for (int nj = 0; nj < 8; nj++)
                    mma16(acc[mi][nj], afr[mi], bfr[nj]);
        }
    }

    // ---- final epilogue: segment mean over 16 edges + b3
    #pragma unroll
    for (int mi = 0; mi < 2; mi++){
        #pragma unroll
        for (int nj = 0; nj < 8; nj++){
            const int cb = wn*64 + nj*8 + 2*tig;
            float s0 = acc[mi][nj][0] + acc[mi][nj][2];
            float s1 = acc[mi][nj][1] + acc[mi][nj][3];
            s0 += __shfl_xor_sync(0xffffffffu, s0, 4);
            s0 += __shfl_xor_sync(0xffffffffu, s0, 8);
            s0 += __shfl_xor_sync(0xffffffffu, s0, 16);
            s1 += __shfl_xor_sync(0xffffffffu, s1, 4);
            s1 += __shfl_xor_sync(0xffffffffu, s1, 8);
            s1 += __shfl_xor_sync(0xffffffffu, s1, 16);
            if (lane < 4){
                const int dst = (m0 + wm*32 + mi*16) >> 4;
                float2 o;
                o.x = s0 * 0.0625f + b3[cb];
                o.y = s1 * 0.0625f + b3[cb+1];
                *(float2*)(out + (size_t)dst*256 + cb) = o;
            }
        }
    }
}

// ---------------------------------------------------------------------------
extern "C" void kernel_launch(void* const* d_in, const int* in_sizes, int n_in,
                              void* d_out, int out_size)
{
    const float* x        = (const float*)d_in[0];
    const float* mesh_pos = (const float*)d_in[1];
    const int*   me32     = (const int*)  d_in[2];
    const float* ip_w1 = (const float*)d_in[4];
    const float* ip_b1 = (const float*)d_in[5];
    const float* ip_w2 = (const float*)d_in[6];
    const float* ip_b2 = (const float*)d_in[7];
    const float* ip_w3 = (const float*)d_in[8];
    const float* ip_b3 = (const float*)d_in[9];
    const float* bf    = (const float*)d_in[10];
    const float* mw1   = (const float*)d_in[11];
    const float* mb1   = (const float*)d_in[12];
    const float* mw2   = (const float*)d_in[13];
    const float* mb2   = (const float*)d_in[14];
    const float* mw3   = (const float*)d_in[15];
    const float* mb3   = (const float*)d_in[16];
    float* out = (float*)d_out;

    __half *h1p, *h2p, *hhp, *eaHp, *w2h, *w3h, *mw1h, *mw2h, *mw3h;
    float  *ebp;
    cudaGetSymbolAddress((void**)&h1p,  g_h1);
    cudaGetSymbolAddress((void**)&h2p,  g_h2a);
    cudaGetSymbolAddress((void**)&hhp,  g_hh);
    cudaGetSymbolAddress((void**)&eaHp, g_eaH);
    cudaGetSymbolAddress((void**)&ebp,  g_eb);
    cudaGetSymbolAddress((void**)&w2h,  g_w2h);
    cudaGetSymbolAddress((void**)&w3h,  g_w3h);
    cudaGetSymbolAddress((void**)&mw1h, g_mw1h);
    cudaGetSymbolAddress((void**)&mw2h, g_mw2h);
    cudaGetSymbolAddress((void**)&mw3h, g_mw3h);

    cudaFuncSetAttribute(gemm16<256,1,true >, cudaFuncAttributeMaxDynamicSharedMemorySize, GEMM_SMEM);
    cudaFuncSetAttribute(gemm16<256,2,true >, cudaFuncAttributeMaxDynamicSharedMemorySize, GEMM_SMEM);
    cudaFuncSetAttribute(gemm16<256,4,false>, cudaFuncAttributeMaxDynamicSharedMemorySize, GEMM_SMEM);
    cudaFuncSetAttribute(gemm16<256,0,true >, cudaFuncAttributeMaxDynamicSharedMemorySize, GEMM_SMEM);
    cudaFuncSetAttribute(edge_fused,          cudaFuncAttributeMaxDynamicSharedMemorySize, GEMM_SMEM);

    detect_kernel<<<1, 32>>>(me32);

    // weight fp16 prep
    f2h_kernel<<<(256*256+255)/256, 256>>>(ip_w2, w2h, 256*256);
    f2h_kernel<<<(256*256+255)/256, 256>>>(ip_w3, w3h, 256*256);
    f2h_kernel<<<(512*512+255)/256, 256>>>(mw1,  mw1h, 512*512);
    f2h_kernel<<<(256*512+255)/256, 256>>>(mw2,  mw2h, 256*512);
    f2h_kernel<<<(256*256+255)/256, 256>>>(mw3,  mw3h, 256*256);

    // node encoder
    h1_kernel<<<N_NODES/64, 256>>>(x, ip_w1, ip_b1);
    gemm16<256,1,true ><<<dim3(N_NODES/128,1), 512, GEMM_SMEM>>>(
        h1p, 256, w2h, 256, ip_b2, h2p, 256, nullptr, nullptr);
    gemm16<256,2,true ><<<dim3(N_NODES/128,1), 512, GEMM_SMEM>>>(
        h2p, 256, w3h, 256, ip_b3, hhp, 256, mesh_pos, bf);

    // hoisted edge layer-1 halves: ea fp16 (no bias), eb fp32 (+b1)
    gemm16<256,4,false><<<dim3(N_NODES/128,2), 512, GEMM_SMEM>>>(
        hhp, 256, mw1h, 512, nullptr, eaHp, 512, nullptr, nullptr);
    gemm16<256,0,true ><<<dim3(N_DST/128,2), 512, GEMM_SMEM>>>(
        hhp, 256, mw1h + 256, 512, mb1, ebp, 512, nullptr, nullptr);

    // fused edge layers 2+3 + segment mean
    edge_fused<<<N_EDGES/128, 512, GEMM_SMEM>>>(
        eaHp, ebp, mw2h, mb2, mw3h, mb3, out, me32);
}

// round 6
// speedup vs baseline: 10.4255x; 1.0578x over previous
#include <cuda_runtime.h>
#include <cuda_fp16.h>
#include <math.h>
#include <stdint.h>

#define N_NODES 131072
#define N_DST   16384
#define DEG     16
#define N_EDGES (N_DST*DEG)
#define HID     256

// ---------------- global scratch (device globals: no runtime alloc) --------
__device__ __align__(16) __half g_h1 [(size_t)N_NODES * 256];
__device__ __align__(16) __half g_h2a[(size_t)N_NODES * 256];
__device__ __align__(16) __half g_hh [(size_t)N_NODES * 256];
__device__ __align__(16) __half g_eaH[(size_t)N_NODES * 512];
__device__ __align__(16) float  g_eb [(size_t)N_DST   * 512];
__device__ __align__(16) __half g_w2h [256*256];
__device__ __align__(16) __half g_w3h [256*256];
__device__ __align__(16) __half g_mw1h[512*512];
__device__ __align__(16) __half g_mw2h[256*512];
__device__ __align__(16) __half g_mw3h[256*256];
__device__ int g_is64;

__device__ __forceinline__ float gelu_exact(float x){
    return 0.5f * x * (1.0f + erff(x * 0.70710678118654752f));
}
__device__ __forceinline__ uint32_t smem_u32(const void* p){
    uint32_t a;
    asm("{ .reg .u64 t; cvta.to.shared.u64 t, %1; cvt.u32.u64 %0, t; }" : "=r"(a) : "l"(p));
    return a;
}
__device__ __forceinline__ void mma16(float* c, const uint32_t* a, const uint32_t* b){
    asm volatile("mma.sync.aligned.m16n8k16.row.col.f32.f16.f16.f32 "
        "{%0,%1,%2,%3}, {%4,%5,%6,%7}, {%8,%9}, {%0,%1,%2,%3};"
        : "+f"(c[0]), "+f"(c[1]), "+f"(c[2]), "+f"(c[3])
        : "r"(a[0]), "r"(a[1]), "r"(a[2]), "r"(a[3]), "r"(b[0]), "r"(b[1]));
}
__device__ __forceinline__ void ldsm4(uint32_t& r0, uint32_t& r1, uint32_t& r2, uint32_t& r3,
                                      uint32_t addr){
    asm volatile("ldmatrix.sync.aligned.m8n8.x4.shared.b16 {%0,%1,%2,%3}, [%4];"
        : "=r"(r0), "=r"(r1), "=r"(r2), "=r"(r3) : "r"(addr));
}
#define CP16(dst, src) \
    asm volatile("cp.async.ca.shared.global [%0], [%1], 16;" :: "r"(dst), "l"(src) : "memory")
#define CP_COMMIT() asm volatile("cp.async.commit_group;" ::: "memory")
#define CP_WAIT2()  asm volatile("cp.async.wait_group 2;"  ::: "memory")
#define CP_WAIT1()  asm volatile("cp.async.wait_group 1;"  ::: "memory")

// ---------------------------------------------------------------------------
__global__ void detect_kernel(const int* __restrict__ me32){
    if (threadIdx.x == 0 && blockIdx.x == 0) g_is64 = (me32[32] != 1) ? 1 : 0;
}

// one-shot fp16 conversion of all five weight matrices (float4 granularity)
__global__ __launch_bounds__(256)
void f2h_all(const float* __restrict__ w2, const float* __restrict__ w3,
             const float* __restrict__ m1, const float* __restrict__ m2,
             const float* __restrict__ m3,
             __half* __restrict__ dw2, __half* __restrict__ dw3,
             __half* __restrict__ dm1, __half* __restrict__ dm2,
             __half* __restrict__ dm3)
{
    int i = blockIdx.x*256 + threadIdx.x;          // float4 index, total 147456
    const float* s; __half* d; int off;
    if      (i <  16384){ s = w2; d = dw2; off = i; }
    else if (i <  32768){ s = w3; d = dw3; off = i - 16384; }
    else if (i <  98304){ s = m1; d = dm1; off = i - 32768; }
    else if (i < 131072){ s = m2; d = dm2; off = i - 98304; }
    else                { s = m3; d = dm3; off = i - 131072; }
    float4 v = ((const float4*)s)[off];
    __half2 h0 = __floats2half2_rn(v.x, v.y), h1 = __floats2half2_rn(v.z, v.w);
    uint2 pk;
    pk.x = *reinterpret_cast<uint32_t*>(&h0);
    pk.y = *reinterpret_cast<uint32_t*>(&h1);
    ((uint2*)d)[off] = pk;
}

// h1 = gelu(x @ W1^T + b1), K=3: fp32 math, fp16 store.
__global__ __launch_bounds__(256)
void h1_kernel(const float* __restrict__ x,
               const float* __restrict__ w1, const float* __restrict__ b1){
    __shared__ float sx[64*3];
    const int t  = threadIdx.x;
    const int n0 = blockIdx.x * 64;
    for (int i = t; i < 64*3; i += 256) sx[i] = x[(size_t)n0*3 + i];
    __syncthreads();
    const float wa = w1[t*3+0], wb = w1[t*3+1], wc = w1[t*3+2], bb = b1[t];
    for (int n = 0; n < 64; n++){
        float v = fmaf(wa, sx[n*3+0], fmaf(wb, sx[n*3+1], fmaf(wc, sx[n*3+2], bb)));
        g_h1[(size_t)(n0+n)*256 + t] = __float2half_rn(gelu_exact(v));
    }
}

// ---------------------------------------------------------------------------
// fp16 mma.sync GEMM: C[M x Ntot] = epi(A[M x K] @ W[Ntot x K]^T + bias)
// Block 128x256, BK=32, 512 threads = 16 warps (4x4), warp tile 32x64.
// 4-stage cp.async pipeline, XOR-swizzled smem, ldmatrix.x4 fragment loads.
// EPI: 0=fp32 store(+bias), 1=gelu->fp16, 2=+fourier->fp16, 4=plain fp16.
// ---------------------------------------------------------------------------
#define GEMM_SMEM (96*1024)

template<int K, int EPI, bool HAS_BIAS>
__global__ __launch_bounds__(512, 1)
void gemm16(const __half* __restrict__ A, int lda,
            const __half* __restrict__ W, int ldw,
            const float* __restrict__ bias,
            void* __restrict__ Cout, int ldc,
            const float* __restrict__ pos,
            const float* __restrict__ bfour)
{
    extern __shared__ char smem[];
    const int t    = threadIdx.x;
    const int lane = t & 31;
    const int w    = t >> 5;
    const int wm   = w >> 2, wn = w & 3;
    const int gid  = lane >> 2, tig = lane & 3;
    const int m0   = blockIdx.x * 128;
    const int n0   = blockIdx.y * 256;
    const uint32_t sb = smem_u32(smem);

    // per-lane ldmatrix base offsets (kb for s=0 baked in; s=1 -> XOR 0x20)
    uint32_t offA[2], offB[4];
    {
        const int l8 = lane & 7;
        const int h3 = (lane >> 3) & 1;
        const int h4 = lane >> 4;
        #pragma unroll
        for (int mi = 0; mi < 2; mi++){
            int rA = wm*32 + mi*16 + h3*8 + l8;
            int sw = (rA >> 1) & 3;
            offA[mi] = (uint32_t)(rA*64) + (uint32_t)((h4 ^ sw) << 4);
        }
        #pragma unroll
        for (int p = 0; p < 4; p++){
            int rB = wn*64 + p*16 + h4*8 + l8;
            int sw = (rB >> 1) & 3;
            offB[p] = (uint32_t)(rB*64) + (uint32_t)((h3 ^ sw) << 4);
        }
    }

    float acc[2][8][4];
    #pragma unroll
    for (int i = 0; i < 2; i++)
        #pragma unroll
        for (int j = 0; j < 8; j++)
            #pragma unroll
            for (int r = 0; r < 4; r++) acc[i][j][r] = 0.f;

    constexpr int NC = K / 32;

    auto produce = [&](int kc){
        const int st = kc & 3;
        const int r = t >> 2, c = t & 3;
        uint32_t dst = sb + st*8192 + r*64 + (uint32_t)((c ^ ((r>>1)&3)) << 4);
        CP16(dst, (const void*)(A + (size_t)(m0 + r)*lda + kc*32 + c*8));
        #pragma unroll
        for (int it = 0; it < 2; it++){
            const int idx = it*512 + t, rr = idx >> 2, cc = idx & 3;
            uint32_t db = sb + 32768 + st*16384 + rr*64 + (uint32_t)((cc ^ ((rr>>1)&3)) << 4);
            CP16(db, (const void*)(W + (size_t)(n0 + rr)*ldw + kc*32 + cc*8));
        }
        CP_COMMIT();
    };

    produce(0); produce(1); produce(2);

    for (int kc = 0; kc < NC; kc++){
        CP_WAIT2();
        __syncthreads();
        const uint32_t aB = sb + (kc & 3)*8192;
        const uint32_t bB = sb + 32768u + (kc & 3)*16384;
        #pragma unroll
        for (int s = 0; s < 2; s++){
            const uint32_t sx = (uint32_t)s << 5;
            uint32_t afr[2][4], bfr[8][2];
            #pragma unroll
            for (int mi = 0; mi < 2; mi++)
                ldsm4(afr[mi][0], afr[mi][1], afr[mi][2], afr[mi][3],
                      aB + (offA[mi] ^ sx));
            #pragma unroll
            for (int p = 0; p < 4; p++)
                ldsm4(bfr[2*p][0], bfr[2*p][1], bfr[2*p+1][0], bfr[2*p+1][1],
                      bB + (offB[p] ^ sx));
            #pragma unroll
            for (int mi = 0; mi < 2; mi++)
                #pragma unroll
                for (int nj = 0; nj < 8; nj++)
                    mma16(acc[mi][nj], afr[mi], bfr[nj]);
        }
        if (kc + 3 < NC) produce(kc + 3); else CP_COMMIT();
    }

    // ---- epilogue ----
    #pragma unroll
    for (int mi = 0; mi < 2; mi++){
        const int r0 = m0 + wm*32 + mi*16 + gid;
        const int r1 = r0 + 8;
        float p00 = 0.f, p01 = 0.f, p10 = 0.f, p11 = 0.f;
        if (EPI == 2){
            p00 = pos[(size_t)r0*2]; p01 = pos[(size_t)r0*2 + 1];
            p10 = pos[(size_t)r1*2]; p11 = pos[(size_t)r1*2 + 1];
        }
        #pragma unroll
        for (int nj = 0; nj < 8; nj++){
            const int cb = n0 + wn*64 + nj*8 + 2*tig;
            float v0 = acc[mi][nj][0], v1 = acc[mi][nj][1];
            float v2 = acc[mi][nj][2], v3 = acc[mi][nj][3];
            if (HAS_BIAS){
                const float b0 = bias[cb], b1 = bias[cb+1];
                v0 += b0; v1 += b1; v2 += b0; v3 += b1;
            }
            if (EPI == 1){
                v0 = gelu_exact(v0); v1 = gelu_exact(v1);
                v2 = gelu_exact(v2); v3 = gelu_exact(v3);
            }
            if (EPI == 2){
                const int o0 = cb & 255, o1 = (cb+1) & 255;
                const float ba0 = bfour[(o0 & 127)*2], bb0 = bfour[(o0 & 127)*2 + 1];
                const float ba1 = bfour[(o1 & 127)*2], bb1 = bfour[(o1 & 127)*2 + 1];
                const float TP = 6.283185307179586f;
                float pl0 = TP*(p00*ba0 + p01*bb0), pl1 = TP*(p00*ba1 + p01*bb1);
                float ph0 = TP*(p10*ba0 + p11*bb0), ph1 = TP*(p10*ba1 + p11*bb1);
                v0 += (o0 < 128) ? __cosf(pl0) : __sinf(pl0);
                v1 += (o1 < 128) ? __cosf(pl1) : __sinf(pl1);
                v2 += (o0 < 128) ? __cosf(ph0) : __sinf(ph0);
                v3 += (o1 < 128) ? __cosf(ph1) : __sinf(ph1);
            }
            if (EPI == 0){
                float* C = (float*)Cout;
                *(float2*)(C + (size_t)r0*ldc + cb) = make_float2(v0, v1);
                *(float2*)(C + (size_t)r1*ldc + cb) = make_float2(v2, v3);
            } else {
                __half* C = (__half*)Cout;
                *(__half2*)(C + (size_t)r0*ldc + cb) = __floats2half2_rn(v0, v1);
                *(__half2*)(C + (size_t)r1*ldc + cb) = __floats2half2_rn(v2, v3);
            }
        }
    }
}

// ---------------------------------------------------------------------------
// Fused edge kernel: per block of 128 edges (= 8 dsts):
//   phase 1: m2 = gelu([gelu(ea[src]+eb[dst])] @ W2^T + b2)   (K=512)  -> SMEM
//   phase 2: m3 = m2 @ W3^T + b3 ; out[dst] = mean_16(m3)     (K=256)
// ---------------------------------------------------------------------------
__global__ __launch_bounds__(512, 1)
void edge_fused(const __half* __restrict__ eaH, const float* __restrict__ ebF,
                const __half* __restrict__ W2, const float* __restrict__ b2,
                const __half* __restrict__ W3, const float* __restrict__ b3,
                float* __restrict__ out, const int* __restrict__ me32)
{
    extern __shared__ char smem[];
    __shared__ int sSrc[128], sDst[128];
    const int t    = threadIdx.x;
    const int lane = t & 31;
    const int w    = t >> 5;
    const int wm   = w >> 2, wn = w & 3;
    const int gid  = lane >> 2, tig = lane & 3;
    const int m0   = blockIdx.x * 128;
    const uint32_t sb = smem_u32(smem);

    if (t < 128){
        const int e = m0 + t; int s, d;
        if (g_is64){ d = me32[4*e]; s = me32[4*e+2]; }
        else       { d = me32[2*e]; s = me32[2*e+1]; }
        sSrc[t] = s; sDst[t] = d;
    }
    __syncthreads();

    // per-lane ldmatrix offsets
    uint32_t offA[2], offB[4], baseM[2];
    int swM[2];
    const int l8 = lane & 7;
    const int h3 = (lane >> 3) & 1;
    const int h4 = lane >> 4;
    #pragma unroll
    for (int mi = 0; mi < 2; mi++){
        int rA = wm*32 + mi*16 + h3*8 + l8;
        int sw = (rA >> 1) & 3;
        offA[mi] = (uint32_t)(rA*64) + (uint32_t)((h4 ^ sw) << 4);
        baseM[mi] = 32768u + (uint32_t)(rA*512);
        swM[mi] = rA & 7;
    }
    #pragma unroll
    for (int p = 0; p < 4; p++){
        int rB = wn*64 + p*16 + h4*8 + l8;
        int sw = (rB >> 1) & 3;
        offB[p] = (uint32_t)(rB*64) + (uint32_t)((h3 ^ sw) << 4);
    }

    float acc[2][8][4];
    #pragma unroll
    for (int i = 0; i < 2; i++)
        #pragma unroll
        for (int j = 0; j < 8; j++)
            #pragma unroll
            for (int r = 0; r < 4; r++) acc[i][j][r] = 0.f;

    // ---- phase 1 producer: A = gelu(ea[src]+eb[dst]) (STS), B = W2 (cp.async)
    auto produce1 = [&](int kc){
        const int st = kc & 3;
        const int r = t >> 2, c = t & 3;
        const int k0 = kc*32 + c*8;
        uint4 av = *(const uint4*)(eaH + (size_t)sSrc[r]*512 + k0);
        const float* pb = ebF + (size_t)sDst[r]*512 + k0;
        float4 e0 = *(const float4*)pb, e1 = *(const float4*)(pb + 4);
        const __half2* ah = (const __half2*)&av;
        float2 f0 = __half22float2(ah[0]), f1 = __half22float2(ah[1]);
        float2 f2 = __half22float2(ah[2]), f3 = __half22float2(ah[3]);
        __half2 h0 = __floats2half2_rn(gelu_exact(f0.x+e0.x), gelu_exact(f0.y+e0.y));
        __half2 h1 = __floats2half2_rn(gelu_exact(f1.x+e0.z), gelu_exact(f1.y+e0.w));
        __half2 h2 = __floats2half2_rn(gelu_exact(f2.x+e1.x), gelu_exact(f2.y+e1.y));
        __half2 h3v = __floats2half2_rn(gelu_exact(f3.x+e1.z), gelu_exact(f3.y+e1.w));
        uint4 pk;
        pk.x = *reinterpret_cast<uint32_t*>(&h0);
        pk.y = *reinterpret_cast<uint32_t*>(&h1);
        pk.z = *reinterpret_cast<uint32_t*>(&h2);
        pk.w = *reinterpret_cast<uint32_t*>(&h3v);
        *(uint4*)(smem + st*8192 + r*64 + ((c ^ ((r>>1)&3)) << 4)) = pk;
        #pragma unroll
        for (int it = 0; it < 2; it++){
            const int idx = it*512 + t, rr = idx >> 2, cc = idx & 3;
            uint32_t db = sb + 32768 + st*16384 + rr*64 + (uint32_t)((cc ^ ((rr>>1)&3)) << 4);
            CP16(db, (const void*)(W2 + (size_t)rr*512 + kc*32 + cc*8));
        }
        CP_COMMIT();
    };

    produce1(0); produce1(1); produce1(2);

    for (int kc = 0; kc < 16; kc++){
        CP_WAIT2();
        __syncthreads();
        const uint32_t aB = sb + (kc & 3)*8192;
        const uint32_t bB = sb + 32768u + (kc & 3)*16384;
        #pragma unroll
        for (int s = 0; s < 2; s++){
            const uint32_t sx = (uint32_t)s << 5;
            uint32_t afr[2][4], bfr[8][2];
            #pragma unroll
            for (int mi = 0; mi < 2; mi++)
                ldsm4(afr[mi][0], afr[mi][1], afr[mi][2], afr[mi][3],
                      aB + (offA[mi] ^ sx));
            #pragma unroll
            for (int p = 0; p < 4; p++)
                ldsm4(bfr[2*p][0], bfr[2*p][1], bfr[2*p+1][0], bfr[2*p+1][1],
                      bB + (offB[p] ^ sx));
            #pragma unroll
            for (int mi = 0; mi < 2; mi++)
                #pragma unroll
                for (int nj = 0; nj < 8; nj++)
                    mma16(acc[mi][nj], afr[mi], bfr[nj]);
        }
        if (kc + 3 < 16) produce1(kc + 3); else CP_COMMIT();
    }

    __syncthreads();   // everyone done with phase-1 tiles

    // ---- phase 2 W3 producer into [0,32KB), 2 stages
    auto produce2 = [&](int kc){
        const int st = kc & 1;
        #pragma unroll
        for (int it = 0; it < 2; it++){
            const int idx = it*512 + t, rr = idx >> 2, cc = idx & 3;
            uint32_t db = sb + st*16384 + rr*64 + (uint32_t)((cc ^ ((rr>>1)&3)) << 4);
            CP16(db, (const void*)(W3 + (size_t)rr*256 + kc*32 + cc*8));
        }
        CP_COMMIT();
    };
    produce2(0);

    // ---- epilogue-1: m2 = gelu(acc + b2) -> fp16 SMEM at [32KB, 96KB)
    #pragma unroll
    for (int mi = 0; mi < 2; mi++){
        const int lr0 = wm*32 + mi*16 + gid;
        const int lr1 = lr0 + 8;
        #pragma unroll
        for (int nj = 0; nj < 8; nj++){
            const int cb = wn*64 + nj*8 + 2*tig;
            const float b0 = b2[cb], b1 = b2[cb+1];
            __half2 lo = __floats2half2_rn(gelu_exact(acc[mi][nj][0] + b0),
                                           gelu_exact(acc[mi][nj][1] + b1));
            __half2 hi = __floats2half2_rn(gelu_exact(acc[mi][nj][2] + b0),
                                           gelu_exact(acc[mi][nj][3] + b1));
            const int blk = cb >> 3;
            *(__half2*)(smem + 32768 + lr0*512 + ((blk ^ (lr0 & 7)) << 4) + 4*tig) = lo;
            *(__half2*)(smem + 32768 + lr1*512 + ((blk ^ (lr1 & 7)) << 4) + 4*tig) = hi;
            acc[mi][nj][0] = 0.f; acc[mi][nj][1] = 0.f;
            acc[mi][nj][2] = 0.f; acc[mi][nj][3] = 0.f;
        }
    }

    // ---- phase 2 main loop (K=256, 8 chunks)
    for (int kc = 0; kc < 8; kc++){
        __syncthreads();                 // prev compute done; m2 visible (kc=0)
        if (kc + 1 < 8) produce2(kc + 1); else CP_COMMIT();
        CP_WAIT1();
        __syncthreads();
        const uint32_t bB = sb + (kc & 1)*16384;
        #pragma unroll
        for (int s = 0; s < 2; s++){
            const uint32_t sx = (uint32_t)s << 5;
            uint32_t afr[2][4], bfr[8][2];
            #pragma unroll
            for (int mi = 0; mi < 2; mi++){
                const int blk = kc*4 + h4;
                const uint32_t offM = (uint32_t)((blk ^ swM[mi]) << 4);
                ldsm4(afr[mi][0], afr[mi][1], afr[mi][2], afr[mi][3],
                      sb + baseM[mi] + (offM ^ sx));
            }
            #pragma unroll
            for (int p = 0; p < 4; p++)
                ldsm4(bfr[2*p][0], bfr[2*p][1], bfr[2*p+1][0], bfr[2*p+1][1],
                      bB + (offB[p] ^ sx));
            #pragma unroll
            for (int mi = 0; mi < 2; mi++)
                #pragma unroll
                for (int nj = 0; nj < 8; nj++)
                    mma16(acc[mi][nj], afr[mi], bfr[nj]);
        }
    }

    // ---- final epilogue: segment mean over 16 edges + b3
    #pragma unroll
    for (int mi = 0; mi < 2; mi++){
        #pragma unroll
        for (int nj = 0; nj < 8; nj++){
            const int cb = wn*64 + nj*8 + 2*tig;
            float s0 = acc[mi][nj][0] + acc[mi][nj][2];
            float s1 = acc[mi][nj][1] + acc[mi][nj][3];
            s0 += __shfl_xor_sync(0xffffffffu, s0, 4);
            s0 += __shfl_xor_sync(0xffffffffu, s0, 8);
            s0 += __shfl_xor_sync(0xffffffffu, s0, 16);
            s1 += __shfl_xor_sync(0xffffffffu, s1, 4);
            s1 += __shfl_xor_sync(0xffffffffu, s1, 8);
            s1 += __shfl_xor_sync(0xffffffffu, s1, 16);
            if (lane < 4){
                const int dst = (m0 + wm*32 + mi*16) >> 4;
                float2 o;
                o.x = s0 * 0.0625f + b3[cb];
                o.y = s1 * 0.0625f + b3[cb+1];
                *(float2*)(out + (size_t)dst*256 + cb) = o;
            }
        }
    }
}

// ---------------------------------------------------------------------------
extern "C" void kernel_launch(void* const* d_in, const int* in_sizes, int n_in,
                              void* d_out, int out_size)
{
    const float* x        = (const float*)d_in[0];
    const float* mesh_pos = (const float*)d_in[1];
    const int*   me32     = (const int*)  d_in[2];
    const float* ip_w1 = (const float*)d_in[4];
    const float* ip_b1 = (const float*)d_in[5];
    const float* ip_w2 = (const float*)d_in[6];
    const float* ip_b2 = (const float*)d_in[7];
    const float* ip_w3 = (const float*)d_in[8];
    const float* ip_b3 = (const float*)d_in[9];
    const float* bf    = (const float*)d_in[10];
    const float* mw1   = (const float*)d_in[11];
    const float* mb1   = (const float*)d_in[12];
    const float* mw2   = (const float*)d_in[13];
    const float* mb2   = (const float*)d_in[14];
    const float* mw3   = (const float*)d_in[15];
    const float* mb3   = (const float*)d_in[16];
    float* out = (float*)d_out;

    __half *h1p, *h2p, *hhp, *eaHp, *w2h, *w3h, *mw1h, *mw2h, *mw3h;
    float  *ebp;
    cudaGetSymbolAddress((void**)&h1p,  g_h1);
    cudaGetSymbolAddress((void**)&h2p,  g_h2a);
    cudaGetSymbolAddress((void**)&hhp,  g_hh);
    cudaGetSymbolAddress((void**)&eaHp, g_eaH);
    cudaGetSymbolAddress((void**)&ebp,  g_eb);
    cudaGetSymbolAddress((void**)&w2h,  g_w2h);
    cudaGetSymbolAddress((void**)&w3h,  g_w3h);
    cudaGetSymbolAddress((void**)&mw1h, g_mw1h);
    cudaGetSymbolAddress((void**)&mw2h, g_mw2h);
    cudaGetSymbolAddress((void**)&mw3h, g_mw3h);

    cudaFuncSetAttribute(gemm16<256,1,true >, cudaFuncAttributeMaxDynamicSharedMemorySize, GEMM_SMEM);
    cudaFuncSetAttribute(gemm16<256,2,true >, cudaFuncAttributeMaxDynamicSharedMemorySize, GEMM_SMEM);
    cudaFuncSetAttribute(gemm16<256,4,false>, cudaFuncAttributeMaxDynamicSharedMemorySize, GEMM_SMEM);
    cudaFuncSetAttribute(gemm16<256,0,true >, cudaFuncAttributeMaxDynamicSharedMemorySize, GEMM_SMEM);
    cudaFuncSetAttribute(edge_fused,          cudaFuncAttributeMaxDynamicSharedMemorySize, GEMM_SMEM);

    detect_kernel<<<1, 32>>>(me32);

    // single fp16 weight prep launch (also aligns ncu -s 5 onto the ea GEMM)
    f2h_all<<<576, 256>>>(ip_w2, ip_w3, mw1, mw2, mw3, w2h, w3h, mw1h, mw2h, mw3h);

    // node encoder
    h1_kernel<<<N_NODES/64, 256>>>(x, ip_w1, ip_b1);
    gemm16<256,1,true ><<<dim3(N_NODES/128,1), 512, GEMM_SMEM>>>(
        h1p, 256, w2h, 256, ip_b2, h2p, 256, nullptr, nullptr);
    gemm16<256,2,true ><<<dim3(N_NODES/128,1), 512, GEMM_SMEM>>>(
        h2p, 256, w3h, 256, ip_b3, hhp, 256, mesh_pos, bf);

    // hoisted edge layer-1 halves: ea fp16 (no bias), eb fp32 (+b1)
    gemm16<256,4,false><<<dim3(N_NODES/128,2), 512, GEMM_SMEM>>>(
        hhp, 256, mw1h, 512, nullptr, eaHp, 512, nullptr, nullptr);
    gemm16<256,0,true ><<<dim3(N_DST/128,2), 512, GEMM_SMEM>>>(
        hhp, 256, mw1h + 256, 512, mb1, ebp, 512, nullptr, nullptr);

    // fused edge layers 2+3 + segment mean
    edge_fused<<<N_EDGES/128, 512, GEMM_SMEM>>>(
        eaHp, ebp, mw2h, mb2, mw3h, mb3, out, me32);
}